// round 1
// baseline (speedup 1.0000x reference)
#include <cuda_runtime.h>
#include <math.h>

#define TT    2048
#define DIMM  2048
#define NH    16
#define HD    128
#define KDIM  2048
#define EPSF  1.1920929e-07f

// ---------------- scratch (device globals: no allocation allowed) ----------
__device__ float g_q[TT * DIMM];
__device__ float g_k[TT * DIMM];
__device__ float g_v[TT * DIMM];
__device__ float g_att[TT * DIMM];
__device__ float g_cos[TT * 64];
__device__ float g_sin[TT * 64];

// ---------------- packed f32x2 helpers (FFMA2 path, sm_103a) ---------------
__device__ __forceinline__ unsigned long long pk2(float lo, float hi) {
    unsigned long long r;
    asm("mov.b64 %0, {%1, %2};" : "=l"(r)
        : "r"(__float_as_uint(lo)), "r"(__float_as_uint(hi)));
    return r;
}
__device__ __forceinline__ unsigned long long fma2(unsigned long long a,
                                                   unsigned long long b,
                                                   unsigned long long c) {
    unsigned long long d;
    asm("fma.rn.f32x2 %0, %1, %2, %3;" : "=l"(d) : "l"(a), "l"(b), "l"(c));
    return d;
}
__device__ __forceinline__ void upk2(unsigned long long v, float& lo, float& hi) {
    unsigned int a, b;
    asm("mov.b64 {%0, %1}, %2;" : "=r"(a), "=r"(b) : "l"(v));
    lo = __uint_as_float(a);
    hi = __uint_as_float(b);
}

// ---------------- SGEMM: C[M,N] = A[M,K] @ B[N,K]^T, 128x128x8 tiles -------
__device__ __forceinline__ void sgemm_tile(const float* __restrict__ A,
                                           const float* __restrict__ B,
                                           float* __restrict__ C) {
    __shared__ float As[8][128];
    __shared__ float Bs[8][128];

    const int tid = threadIdx.x;
    const int tx = tid & 15;
    const int ty = tid >> 4;
    const int mBase = blockIdx.y * 128;
    const int nBase = blockIdx.x * 128;

    const int lrow = tid >> 1;
    const int lk4 = (tid & 1) * 4;

    const float4* Ap = (const float4*)(A + (size_t)(mBase + lrow) * KDIM + lk4);
    const float4* Bp = (const float4*)(B + (size_t)(nBase + lrow) * KDIM + lk4);

    unsigned long long acc[8][4];
#pragma unroll
    for (int i = 0; i < 8; i++)
#pragma unroll
        for (int j = 0; j < 4; j++) acc[i][j] = 0ull;

    float4 av = Ap[0];
    float4 bv = Bp[0];

    for (int k0 = 0; k0 < KDIM; k0 += 8) {
        As[lk4 + 0][lrow] = av.x;
        As[lk4 + 1][lrow] = av.y;
        As[lk4 + 2][lrow] = av.z;
        As[lk4 + 3][lrow] = av.w;
        Bs[lk4 + 0][lrow] = bv.x;
        Bs[lk4 + 1][lrow] = bv.y;
        Bs[lk4 + 2][lrow] = bv.z;
        Bs[lk4 + 3][lrow] = bv.w;
        __syncthreads();

        if (k0 + 8 < KDIM) {
            av = Ap[(k0 + 8) >> 2];
            bv = Bp[(k0 + 8) >> 2];
        }

#pragma unroll
        for (int k = 0; k < 8; k++) {
            float4 a0 = *(const float4*)&As[k][ty * 4];
            float4 a1 = *(const float4*)&As[k][ty * 4 + 64];
            float4 b0 = *(const float4*)&Bs[k][tx * 4];
            float4 b1 = *(const float4*)&Bs[k][tx * 4 + 64];
            unsigned long long bp[4];
            bp[0] = pk2(b0.x, b0.y);
            bp[1] = pk2(b0.z, b0.w);
            bp[2] = pk2(b1.x, b1.y);
            bp[3] = pk2(b1.z, b1.w);
            float ar[8] = {a0.x, a0.y, a0.z, a0.w, a1.x, a1.y, a1.z, a1.w};
#pragma unroll
            for (int i = 0; i < 8; i++) {
                unsigned long long ap = pk2(ar[i], ar[i]);
#pragma unroll
                for (int j = 0; j < 4; j++) acc[i][j] = fma2(ap, bp[j], acc[i][j]);
            }
        }
        __syncthreads();
    }

#pragma unroll
    for (int i = 0; i < 8; i++) {
        int m = mBase + ((i < 4) ? (ty * 4 + i) : (64 + ty * 4 + i - 4));
#pragma unroll
        for (int j = 0; j < 4; j++) {
            int c = nBase + ((j < 2) ? (tx * 4 + 2 * j) : (64 + tx * 4 + 2 * (j - 2)));
            float lo, hi;
            upk2(acc[i][j], lo, hi);
            *(float2*)&C[(size_t)m * DIMM + c] = make_float2(lo, hi);
        }
    }
}

__global__ __launch_bounds__(256) void qkv_kernel(const float* __restrict__ x,
                                                  const float* __restrict__ Wq,
                                                  const float* __restrict__ Wk,
                                                  const float* __restrict__ Wv) {
    const float* B = (blockIdx.z == 0) ? Wq : ((blockIdx.z == 1) ? Wk : Wv);
    float* C = (blockIdx.z == 0) ? g_q : ((blockIdx.z == 1) ? g_k : g_v);
    sgemm_tile(x, B, C);
}

__global__ __launch_bounds__(256) void proj_kernel(const float* __restrict__ W,
                                                   float* __restrict__ out) {
    sgemm_tile(g_att, W, out);
}

// ---------------- RoPE cos/sin table (matches jax f32 arg, accurate trig) --
__global__ void rope_table() {
    int idx = blockIdx.x * blockDim.x + threadIdx.x;
    if (idx >= TT * 64) return;
    int t = idx >> 6;
    int i = idx & 63;
    float e = (float)(2 * i) * (1.0f / 128.0f);
    float invf = 1.0f / powf(10000.0f, e);
    float fr = (float)t * invf;
    g_cos[idx] = (float)cos((double)fr);
    g_sin[idx] = (float)sin((double)fr);
}

// ---------------- v-mix + per-head RMS norm + RoPE -------------------------
__global__ __launch_bounds__(256) void post_qkv(const float* __restrict__ v1,
                                                const float* __restrict__ lambp) {
    const int t = blockIdx.x;
    const int tid = threadIdx.x;
    const float lamb = *lambp;

    float* vrow = g_v + (size_t)t * DIMM;
    const float* v1row = v1 + (size_t)t * DIMM;
    for (int i = tid; i < DIMM; i += 256)
        vrow[i] = (1.0f - lamb) * vrow[i] + lamb * v1row[i];

    const int warp = tid >> 5;
    const int lane = tid & 31;

    for (int hh = warp; hh < 2 * NH; hh += 8) {
        float* p = ((hh & 1) ? g_k : g_q) + (size_t)t * DIMM + (hh >> 1) * HD;
        // RMS: warp-reduce sum of squares over 128 dims
        float4 f = *(const float4*)&p[lane * 4];
        float ss = f.x * f.x + f.y * f.y + f.z * f.z + f.w * f.w;
#pragma unroll
        for (int off = 16; off; off >>= 1) ss += __shfl_xor_sync(0xffffffffu, ss, off);
        float sc = rsqrtf(ss * (1.0f / 128.0f) + EPSF);
        __syncwarp();
        // RoPE: lane owns dims {lane, lane+64} and {lane+32, lane+96}
#pragma unroll
        for (int rep = 0; rep < 2; rep++) {
            int i = lane + rep * 32;
            float x1 = p[i] * sc;
            float x2 = p[i + 64] * sc;
            float c = g_cos[t * 64 + i];
            float s = g_sin[t * 64 + i];
            p[i] = x1 * c + x2 * s;
            p[i + 64] = x2 * c - x1 * s;
        }
    }
}

// ---------------- flash attention (fp32, BQ=BK=64, f32x2 math) -------------
#define BQ 64
#define BKT 64
#define FLASH_SMEM ((2 * 64 * 129 + 64 * 132 + 64 * 65 + 3 * 64) * 4)

__global__ __launch_bounds__(256) void flash_kernel() {
    extern __shared__ float sm[];
    float(*Qs)[129] = (float(*)[129])sm;                    // 64x129
    float(*Ks)[129] = (float(*)[129])(sm + 64 * 129);       // 64x129
    float(*Vs)[132] = (float(*)[132])(sm + 2 * 64 * 129);   // 64x132 (float4-aligned rows)
    float(*Ss)[65] = (float(*)[65])(sm + 2 * 64 * 129 + 64 * 132);
    float* row_m = sm + 2 * 64 * 129 + 64 * 132 + 64 * 65;
    float* row_l = row_m + 64;
    float* row_a = row_l + 64;

    const int h = blockIdx.y;
    const int qb = gridDim.x - 1 - blockIdx.x;  // heavy tiles first
    const int q0 = qb * BQ;
    const int tid = threadIdx.x;
    const int tx = tid & 15;
    const int ty = tid >> 4;

    const float* Qg = g_q + h * HD;
    const float* Kg = g_k + h * HD;
    const float* Vg = g_v + h * HD;

    for (int idx = tid; idx < BQ * HD; idx += 256) {
        int r = idx >> 7, c = idx & 127;
        Qs[r][c] = Qg[(size_t)(q0 + r) * DIMM + c];
    }
    if (tid < 64) {
        row_m[tid] = -INFINITY;
        row_l[tid] = 0.0f;
    }

    unsigned long long o2[4][4];
#pragma unroll
    for (int i = 0; i < 4; i++)
#pragma unroll
        for (int c = 0; c < 4; c++) o2[i][c] = 0ull;

    const float scale = 0.08838834764831845f;  // 1/sqrt(128)

    for (int kb = 0; kb <= qb; kb++) {
        const int s0 = kb * BKT;
        __syncthreads();
        for (int idx = tid; idx < BKT * HD; idx += 256) {
            int r = idx >> 7, c = idx & 127;
            Ks[r][c] = Kg[(size_t)(s0 + r) * DIMM + c];
            Vs[r][c] = Vg[(size_t)(s0 + r) * DIMM + c];
        }
        __syncthreads();

        // S = (Q K^T), 4x4 frag per thread via f32x2
        unsigned long long s2[4][2];
#pragma unroll
        for (int i = 0; i < 4; i++) { s2[i][0] = 0ull; s2[i][1] = 0ull; }

#pragma unroll 4
        for (int kk = 0; kk < HD; kk++) {
            float qv[4], kv[4];
#pragma unroll
            for (int i = 0; i < 4; i++) {
                qv[i] = Qs[ty * 4 + i][kk];
                kv[i] = Ks[tx * 4 + i][kk];
            }
            unsigned long long bp0 = pk2(kv[0], kv[1]);
            unsigned long long bp1 = pk2(kv[2], kv[3]);
#pragma unroll
            for (int i = 0; i < 4; i++) {
                unsigned long long ap = pk2(qv[i], qv[i]);
                s2[i][0] = fma2(ap, bp0, s2[i][0]);
                s2[i][1] = fma2(ap, bp1, s2[i][1]);
            }
        }

        // scale + causal mask -> Ss
#pragma unroll
        for (int i = 0; i < 4; i++) {
            int gr = q0 + ty * 4 + i;
#pragma unroll
            for (int jj = 0; jj < 2; jj++) {
                float lo, hi;
                upk2(s2[i][jj], lo, hi);
                int c0 = tx * 4 + 2 * jj;
                Ss[ty * 4 + i][c0] = (s0 + c0 <= gr) ? lo * scale : -1e30f;
                Ss[ty * 4 + i][c0 + 1] = (s0 + c0 + 1 <= gr) ? hi * scale : -1e30f;
            }
        }
        __syncthreads();

        // online softmax (one thread per row)
        if (tid < 64) {
            float mold = row_m[tid];
            float mt = mold;
#pragma unroll 8
            for (int j = 0; j < BKT; j++) mt = fmaxf(mt, Ss[tid][j]);
            float al = __expf(mold - mt);
            float sum = 0.0f;
#pragma unroll 8
            for (int j = 0; j < BKT; j++) {
                float pv = __expf(Ss[tid][j] - mt);
                Ss[tid][j] = pv;
                sum += pv;
            }
            row_l[tid] = row_l[tid] * al + sum;
            row_m[tid] = mt;
            row_a[tid] = al;
        }
        __syncthreads();

        // O = O*alpha + P @ V   (4 rows x 8 cols per thread, packed)
        float al[4];
#pragma unroll
        for (int i = 0; i < 4; i++) al[i] = row_a[ty * 4 + i];
#pragma unroll
        for (int i = 0; i < 4; i++) {
            unsigned long long ap = pk2(al[i], al[i]);
#pragma unroll
            for (int c = 0; c < 4; c++) o2[i][c] = fma2(o2[i][c], ap, 0ull);
        }
#pragma unroll 2
        for (int j = 0; j < BKT; j++) {
            float4 v0 = *(const float4*)&Vs[j][tx * 8];
            float4 v1v = *(const float4*)&Vs[j][tx * 8 + 4];
            unsigned long long vp[4];
            vp[0] = pk2(v0.x, v0.y);
            vp[1] = pk2(v0.z, v0.w);
            vp[2] = pk2(v1v.x, v1v.y);
            vp[3] = pk2(v1v.z, v1v.w);
#pragma unroll
            for (int i = 0; i < 4; i++) {
                float pv = Ss[ty * 4 + i][j];
                unsigned long long pp = pk2(pv, pv);
#pragma unroll
                for (int c = 0; c < 4; c++) o2[i][c] = fma2(pp, vp[c], o2[i][c]);
            }
        }
    }

    // normalize + store
    float linv[4];
#pragma unroll
    for (int i = 0; i < 4; i++) linv[i] = 1.0f / row_l[ty * 4 + i];
#pragma unroll
    for (int i = 0; i < 4; i++) {
        float ov[8];
#pragma unroll
        for (int c = 0; c < 4; c++) upk2(o2[i][c], ov[2 * c], ov[2 * c + 1]);
#pragma unroll
        for (int e = 0; e < 8; e++) ov[e] *= linv[i];
        float4* dst = (float4*)&g_att[(size_t)(q0 + ty * 4 + i) * DIMM + h * HD + tx * 8];
        dst[0] = make_float4(ov[0], ov[1], ov[2], ov[3]);
        dst[1] = make_float4(ov[4], ov[5], ov[6], ov[7]);
    }
}

// ---------------- v1 passthrough -------------------------------------------
__global__ void copy_v1(const float4* __restrict__ src, float4* __restrict__ dst, int n4) {
    int idx = blockIdx.x * blockDim.x + threadIdx.x;
    if (idx < n4) dst[idx] = src[idx];
}

// ---------------- launch ----------------------------------------------------
extern "C" void kernel_launch(void* const* d_in, const int* in_sizes, int n_in,
                              void* d_out, int out_size) {
    const float* x = (const float*)d_in[0];
    const float* v1 = (const float*)d_in[1];
    const float* Wq = (const float*)d_in[2];
    const float* Wk = (const float*)d_in[3];
    const float* Wv = (const float*)d_in[4];
    const float* Wp = (const float*)d_in[5];
    const float* lamb = (const float*)d_in[6];
    float* out = (float*)d_out;

    rope_table<<<(TT * 64 + 255) / 256, 256>>>();

    dim3 gqkv(DIMM / 128, TT / 128, 3);
    qkv_kernel<<<gqkv, 256>>>(x, Wq, Wk, Wv);

    post_qkv<<<TT, 256>>>(v1, lamb);

    cudaFuncSetAttribute(flash_kernel, cudaFuncAttributeMaxDynamicSharedMemorySize,
                         FLASH_SMEM);
    dim3 gfl(TT / BQ, NH);
    flash_kernel<<<gfl, 256, FLASH_SMEM>>>();

    dim3 gproj(DIMM / 128, TT / 128);
    proj_kernel<<<gproj, 256>>>(Wp, out);

    if (out_size >= 2 * TT * DIMM) {
        copy_v1<<<(TT * DIMM / 4 + 255) / 256, 256>>>(
            (const float4*)v1, (float4*)(out + (size_t)TT * DIMM), TT * DIMM / 4);
    }
}

// round 4
// speedup vs baseline: 1.4131x; 1.4131x over previous
#include <cuda_runtime.h>
#include <cuda_bf16.h>
#include <math.h>
#include <stdint.h>

#define TT    2048
#define DIMM  2048
#define NH    16
#define HD    128
#define EPSF  1.1920929e-07f

// ---------------- scratch (device globals: no allocation allowed) ----------
__device__ float g_q[TT * DIMM];
__device__ float g_k[TT * DIMM];
__device__ float g_v[TT * DIMM];
__device__ float g_att[TT * DIMM];
__device__ float g_cos[TT * 64];
__device__ float g_sin[TT * 64];

// split-precision bf16 operands for mma GEMMs
__device__ __nv_bfloat16 g_xh[TT * DIMM],    g_xl[TT * DIMM];
__device__ __nv_bfloat16 g_wqh[DIMM * DIMM], g_wql[DIMM * DIMM];
__device__ __nv_bfloat16 g_wkh[DIMM * DIMM], g_wkl[DIMM * DIMM];
__device__ __nv_bfloat16 g_wvh[DIMM * DIMM], g_wvl[DIMM * DIMM];
__device__ __nv_bfloat16 g_wph[DIMM * DIMM], g_wpl[DIMM * DIMM];
__device__ __nv_bfloat16 g_ah[TT * DIMM],    g_al[TT * DIMM];

// ---------------- baseline-PTX helpers -------------------------------------
__device__ __forceinline__ uint32_t smem_u32(const void* p) {
    uint32_t a;
    asm("{ .reg .u64 t; cvta.to.shared.u64 t, %1; cvt.u32.u64 %0, t; }"
        : "=r"(a) : "l"(p));
    return a;
}
__device__ __forceinline__ void cp16(uint32_t dst, const void* src) {
    asm volatile("cp.async.cg.shared.global [%0], [%1], 16;"
                 :: "r"(dst), "l"(src) : "memory");
}
__device__ __forceinline__ void cp_commit() {
    asm volatile("cp.async.commit_group;" ::: "memory");
}
__device__ __forceinline__ void cp_wait1() {
    asm volatile("cp.async.wait_group 1;" ::: "memory");
}
__device__ __forceinline__ void cp_wait0() {
    asm volatile("cp.async.wait_group 0;" ::: "memory");
}

#define LDM_X4(r0, r1, r2, r3, a)                                              \
    asm volatile("ldmatrix.sync.aligned.m8n8.x4.shared.b16 {%0,%1,%2,%3},[%4];"\
                 : "=r"(r0), "=r"(r1), "=r"(r2), "=r"(r3) : "r"(a))
#define LDM_X2(r0, r1, a)                                                      \
    asm volatile("ldmatrix.sync.aligned.m8n8.x2.shared.b16 {%0,%1},[%2];"      \
                 : "=r"(r0), "=r"(r1) : "r"(a))

#define MMA_BF16(c, a, b)                                                      \
    asm volatile(                                                              \
        "mma.sync.aligned.m16n8k16.row.col.f32.bf16.bf16.f32 "                 \
        "{%0,%1,%2,%3},{%4,%5,%6,%7},{%8,%9},{%0,%1,%2,%3};"                   \
        : "+f"((c)[0]), "+f"((c)[1]), "+f"((c)[2]), "+f"((c)[3])               \
        : "r"((a)[0]), "r"((a)[1]), "r"((a)[2]), "r"((a)[3]),                  \
          "r"((b)[0]), "r"((b)[1]))

// ---------------- fp32 -> bf16 hi/lo conversion ----------------------------
__global__ __launch_bounds__(256) void cvt_kernel(const float4* __restrict__ src,
                                                  int which) {
    __nv_bfloat16* hi;
    __nv_bfloat16* lo;
    switch (which) {
        case 0: hi = g_xh;  lo = g_xl;  break;
        case 1: hi = g_wqh; lo = g_wql; break;
        case 2: hi = g_wkh; lo = g_wkl; break;
        case 3: hi = g_wvh; lo = g_wvl; break;
        case 4: hi = g_wph; lo = g_wpl; break;
        default: hi = g_ah; lo = g_al; src = (const float4*)g_att; break;
    }
    int i = blockIdx.x * blockDim.x + threadIdx.x;
    if (i >= TT * DIMM / 4) return;
    float4 v = src[i];
    __nv_bfloat16 h[4], l[4];
    h[0] = __float2bfloat16_rn(v.x); l[0] = __float2bfloat16_rn(v.x - __bfloat162float(h[0]));
    h[1] = __float2bfloat16_rn(v.y); l[1] = __float2bfloat16_rn(v.y - __bfloat162float(h[1]));
    h[2] = __float2bfloat16_rn(v.z); l[2] = __float2bfloat16_rn(v.z - __bfloat162float(h[2]));
    h[3] = __float2bfloat16_rn(v.w); l[3] = __float2bfloat16_rn(v.w - __bfloat162float(h[3]));
    ((uint2*)hi)[i] = *(uint2*)h;
    ((uint2*)lo)[i] = *(uint2*)l;
}

// ---------------- mma.sync GEMM: C[M,N] = A @ B^T (both [*,K] K-major) -----
// 128x128 tile, K-chunk 32, double-buffered cp.async. 3-term split bf16.
// SMEM rows: 64B data at 80B stride (conflict-free: bank = r*20+c mod 32).
#define GROW   80
#define GTILE  (128 * GROW)      // 10240 B per operand tile
#define GSTAGE (4 * GTILE)       // Ahi, Alo, Bhi, Blo = 40960 B
#define GSMEM  (2 * GSTAGE)      // 81920 B

__device__ __forceinline__ void g_load_chunk(
    uint32_t base, const __nv_bfloat16* Ah, const __nv_bfloat16* Al,
    const __nv_bfloat16* Bh, const __nv_bfloat16* Bl,
    int mBase, int nBase, int kc, int tid) {
#pragma unroll
    for (int j = 0; j < 8; j++) {
        const int t = j >> 1;
        const int rem = tid + (j & 1) * 256;
        const int r = rem >> 2;
        const int u = rem & 3;
        const __nv_bfloat16* s = (t == 0) ? Ah : (t == 1) ? Al : (t == 2) ? Bh : Bl;
        const int rb = (t < 2) ? mBase : nBase;
        cp16(base + t * GTILE + r * GROW + u * 16,
             s + (size_t)(rb + r) * DIMM + kc + u * 8);
    }
}

__device__ __forceinline__ void gemm_mma(const __nv_bfloat16* Ah, const __nv_bfloat16* Al,
                                         const __nv_bfloat16* Bh, const __nv_bfloat16* Bl,
                                         float* __restrict__ C) {
    extern __shared__ char sm[];
    const uint32_t smb = smem_u32(sm);
    const int tid = threadIdx.x;
    const int wid = tid >> 5;
    const int lane = tid & 31;
    const int mBase = blockIdx.y * 128;
    const int nBase = blockIdx.x * 128;
    const int wm = (wid >> 2) * 64;   // warp m-offset within tile
    const int wn = (wid & 3) * 32;    // warp n-offset within tile

    // per-thread ldmatrix address components
    const int rowA = ((lane >> 3) & 1) * 8 + (lane & 7);  // + piece>>1 selects 16B col
    const int colA = (lane >> 4) * 16;
    const int rowB = lane & 7;
    const int colB = ((lane >> 3) & 1) * 16;

    float acc[4][4][4];
#pragma unroll
    for (int i = 0; i < 4; i++)
#pragma unroll
        for (int n = 0; n < 4; n++)
#pragma unroll
            for (int v = 0; v < 4; v++) acc[i][n][v] = 0.0f;

    g_load_chunk(smb, Ah, Al, Bh, Bl, mBase, nBase, 0, tid);
    cp_commit();

    for (int c = 0; c < 64; c++) {
        const uint32_t cur = smb + (c & 1) * GSTAGE;
        if (c + 1 < 64) {
            g_load_chunk(smb + ((c + 1) & 1) * GSTAGE, Ah, Al, Bh, Bl,
                         mBase, nBase, (c + 1) * 32, tid);
            cp_commit();
            cp_wait1();
        } else {
            cp_wait0();
        }
        __syncthreads();

        const uint32_t Ab = cur;
        const uint32_t Alb = cur + GTILE;
        const uint32_t Bb = cur + 2 * GTILE;
        const uint32_t Blb = cur + 3 * GTILE;

#pragma unroll
        for (int s = 0; s < 2; s++) {
            uint32_t ah[4][4], al2[4][4], bh[4][2], bl[4][2];
#pragma unroll
            for (int i = 0; i < 4; i++)
                LDM_X4(ah[i][0], ah[i][1], ah[i][2], ah[i][3],
                       Ab + (wm + i * 16 + rowA) * GROW + s * 32 + colA);
#pragma unroll
            for (int n = 0; n < 4; n++)
                LDM_X2(bh[n][0], bh[n][1],
                       Bb + (wn + n * 8 + rowB) * GROW + s * 32 + colB);
#pragma unroll
            for (int i = 0; i < 4; i++)
#pragma unroll
                for (int n = 0; n < 4; n++) MMA_BF16(acc[i][n], ah[i], bh[n]);

#pragma unroll
            for (int n = 0; n < 4; n++)
                LDM_X2(bl[n][0], bl[n][1],
                       Blb + (wn + n * 8 + rowB) * GROW + s * 32 + colB);
#pragma unroll
            for (int i = 0; i < 4; i++)
#pragma unroll
                for (int n = 0; n < 4; n++) MMA_BF16(acc[i][n], ah[i], bl[n]);

#pragma unroll
            for (int i = 0; i < 4; i++)
                LDM_X4(al2[i][0], al2[i][1], al2[i][2], al2[i][3],
                       Alb + (wm + i * 16 + rowA) * GROW + s * 32 + colA);
#pragma unroll
            for (int i = 0; i < 4; i++)
#pragma unroll
                for (int n = 0; n < 4; n++) MMA_BF16(acc[i][n], al2[i], bh[n]);
        }
        __syncthreads();
    }

    // epilogue
    const int r0 = mBase + wm + (lane >> 2);
    const int c0 = nBase + wn + (lane & 3) * 2;
#pragma unroll
    for (int i = 0; i < 4; i++)
#pragma unroll
        for (int n = 0; n < 4; n++) {
            *(float2*)&C[(size_t)(r0 + i * 16) * DIMM + c0 + n * 8] =
                make_float2(acc[i][n][0], acc[i][n][1]);
            *(float2*)&C[(size_t)(r0 + i * 16 + 8) * DIMM + c0 + n * 8] =
                make_float2(acc[i][n][2], acc[i][n][3]);
        }
}

__global__ __launch_bounds__(256) void qkv_mma() {
    if (blockIdx.z == 0)      gemm_mma(g_xh, g_xl, g_wqh, g_wql, g_q);
    else if (blockIdx.z == 1) gemm_mma(g_xh, g_xl, g_wkh, g_wkl, g_k);
    else                      gemm_mma(g_xh, g_xl, g_wvh, g_wvl, g_v);
}

__global__ __launch_bounds__(256) void proj_mma(float* __restrict__ out) {
    gemm_mma(g_ah, g_al, g_wph, g_wpl, out);
}

// ---------------- RoPE cos/sin table ---------------------------------------
__global__ void rope_table() {
    int idx = blockIdx.x * blockDim.x + threadIdx.x;
    if (idx >= TT * 64) return;
    int t = idx >> 6;
    int i = idx & 63;
    float e = (float)(2 * i) * (1.0f / 128.0f);
    float invf = 1.0f / powf(10000.0f, e);
    float fr = (float)t * invf;
    g_cos[idx] = (float)cos((double)fr);
    g_sin[idx] = (float)sin((double)fr);
}

// ---------------- v-mix + per-head RMS norm + RoPE -------------------------
__global__ __launch_bounds__(256) void post_qkv(const float* __restrict__ v1,
                                                const float* __restrict__ lambp) {
    const int t = blockIdx.x;
    const int tid = threadIdx.x;
    const float lamb = *lambp;

    float* vrow = g_v + (size_t)t * DIMM;
    const float* v1row = v1 + (size_t)t * DIMM;
    for (int i = tid; i < DIMM; i += 256)
        vrow[i] = (1.0f - lamb) * vrow[i] + lamb * v1row[i];

    const int warp = tid >> 5;
    const int lane = tid & 31;

    for (int hh = warp; hh < 2 * NH; hh += 8) {
        float* p = ((hh & 1) ? g_k : g_q) + (size_t)t * DIMM + (hh >> 1) * HD;
        float4 f = *(const float4*)&p[lane * 4];
        float ss = f.x * f.x + f.y * f.y + f.z * f.z + f.w * f.w;
#pragma unroll
        for (int off = 16; off; off >>= 1) ss += __shfl_xor_sync(0xffffffffu, ss, off);
        float sc = rsqrtf(ss * (1.0f / 128.0f) + EPSF);
        __syncwarp();
#pragma unroll
        for (int rep = 0; rep < 2; rep++) {
            int i = lane + rep * 32;
            float x1 = p[i] * sc;
            float x2 = p[i + 64] * sc;
            float c = g_cos[t * 64 + i];
            float s = g_sin[t * 64 + i];
            p[i] = x1 * c + x2 * s;
            p[i + 64] = x2 * c - x1 * s;
        }
    }
}

// ---------------- packed f32x2 helpers -------------------------------------
__device__ __forceinline__ unsigned long long pk2(float lo, float hi) {
    unsigned long long r;
    asm("mov.b64 %0, {%1, %2};" : "=l"(r)
        : "r"(__float_as_uint(lo)), "r"(__float_as_uint(hi)));
    return r;
}
__device__ __forceinline__ unsigned long long fma2(unsigned long long a,
                                                   unsigned long long b,
                                                   unsigned long long c) {
    unsigned long long d;
    asm("fma.rn.f32x2 %0, %1, %2, %3;" : "=l"(d) : "l"(a), "l"(b), "l"(c));
    return d;
}
__device__ __forceinline__ void upk2(unsigned long long v, float& lo, float& hi) {
    unsigned int a, b;
    asm("mov.b64 {%0, %1}, %2;" : "=r"(a), "=r"(b) : "l"(v));
    lo = __uint_as_float(a);
    hi = __uint_as_float(b);
}

// ---------------- flash attention (fp32, BQ=BK=64, f32x2 math) -------------
#define BQ 64
#define BKT 64
#define SS_STRIDE 68
#define FLASH_SMEM ((2 * 64 * 129 + 64 * 132 + 64 * SS_STRIDE + 3 * 64) * 4)

__global__ __launch_bounds__(256) void flash_kernel() {
    extern __shared__ float smf[];
    float(*Qs)[129] = (float(*)[129])smf;
    float(*Ks)[129] = (float(*)[129])(smf + 64 * 129);
    float(*Vs)[132] = (float(*)[132])(smf + 2 * 64 * 129);
    float(*Ss)[SS_STRIDE] = (float(*)[SS_STRIDE])(smf + 2 * 64 * 129 + 64 * 132);
    float* row_m = smf + 2 * 64 * 129 + 64 * 132 + 64 * SS_STRIDE;
    float* row_l = row_m + 64;
    float* row_a = row_l + 64;

    const int h = blockIdx.y;
    const int qb = gridDim.x - 1 - blockIdx.x;
    const int q0 = qb * BQ;
    const int tid = threadIdx.x;
    const int tx = tid & 15;
    const int ty = tid >> 4;

    const float* Qg = g_q + h * HD;
    const float* Kg = g_k + h * HD;
    const float* Vg = g_v + h * HD;

    for (int idx = tid; idx < BQ * HD; idx += 256) {
        int r = idx >> 7, c = idx & 127;
        Qs[r][c] = Qg[(size_t)(q0 + r) * DIMM + c];
    }
    if (tid < 64) {
        row_m[tid] = -INFINITY;
        row_l[tid] = 0.0f;
    }

    unsigned long long o2[4][4];
#pragma unroll
    for (int i = 0; i < 4; i++)
#pragma unroll
        for (int c = 0; c < 4; c++) o2[i][c] = 0ull;

    const float scale = 0.08838834764831845f;

    for (int kb = 0; kb <= qb; kb++) {
        const int s0 = kb * BKT;
        __syncthreads();
        for (int idx = tid; idx < BKT * HD; idx += 256) {
            int r = idx >> 7, c = idx & 127;
            Ks[r][c] = Kg[(size_t)(s0 + r) * DIMM + c];
            Vs[r][c] = Vg[(size_t)(s0 + r) * DIMM + c];
        }
        __syncthreads();

        unsigned long long s2[4][2];
#pragma unroll
        for (int i = 0; i < 4; i++) { s2[i][0] = 0ull; s2[i][1] = 0ull; }

#pragma unroll 4
        for (int kk = 0; kk < HD; kk++) {
            float qv[4], kv[4];
#pragma unroll
            for (int i = 0; i < 4; i++) {
                qv[i] = Qs[ty * 4 + i][kk];
                kv[i] = Ks[tx * 4 + i][kk];
            }
            unsigned long long bp0 = pk2(kv[0], kv[1]);
            unsigned long long bp1 = pk2(kv[2], kv[3]);
#pragma unroll
            for (int i = 0; i < 4; i++) {
                unsigned long long ap = pk2(qv[i], qv[i]);
                s2[i][0] = fma2(ap, bp0, s2[i][0]);
                s2[i][1] = fma2(ap, bp1, s2[i][1]);
            }
        }

#pragma unroll
        for (int i = 0; i < 4; i++) {
            int gr = q0 + ty * 4 + i;
#pragma unroll
            for (int jj = 0; jj < 2; jj++) {
                float lo, hi;
                upk2(s2[i][jj], lo, hi);
                int c0 = tx * 4 + 2 * jj;
                Ss[ty * 4 + i][c0] = (s0 + c0 <= gr) ? lo * scale : -1e30f;
                Ss[ty * 4 + i][c0 + 1] = (s0 + c0 + 1 <= gr) ? hi * scale : -1e30f;
            }
        }
        __syncthreads();

        // online softmax: 4 threads per row, quad shfl reductions
        {
            const int row = tid >> 2;
            const int sub = tid & 3;
            float mold = row_m[row];
            float mt = mold;
#pragma unroll
            for (int j = 0; j < 16; j++) mt = fmaxf(mt, Ss[row][sub + j * 4]);
            mt = fmaxf(mt, __shfl_xor_sync(0xffffffffu, mt, 1));
            mt = fmaxf(mt, __shfl_xor_sync(0xffffffffu, mt, 2));
            float sum = 0.0f;
#pragma unroll
            for (int j = 0; j < 16; j++) {
                float pv = __expf(Ss[row][sub + j * 4] - mt);
                Ss[row][sub + j * 4] = pv;
                sum += pv;
            }
            sum += __shfl_xor_sync(0xffffffffu, sum, 1);
            sum += __shfl_xor_sync(0xffffffffu, sum, 2);
            if (sub == 0) {
                float al = __expf(mold - mt);
                row_l[row] = row_l[row] * al + sum;
                row_m[row] = mt;
                row_a[row] = al;
            }
        }
        __syncthreads();

        float al[4];
#pragma unroll
        for (int i = 0; i < 4; i++) al[i] = row_a[ty * 4 + i];
#pragma unroll
        for (int i = 0; i < 4; i++) {
            unsigned long long ap = pk2(al[i], al[i]);
#pragma unroll
            for (int c = 0; c < 4; c++) o2[i][c] = fma2(o2[i][c], ap, 0ull);
        }
#pragma unroll 2
        for (int j = 0; j < BKT; j++) {
            float4 v0 = *(const float4*)&Vs[j][tx * 8];
            float4 v1v = *(const float4*)&Vs[j][tx * 8 + 4];
            unsigned long long vp[4];
            vp[0] = pk2(v0.x, v0.y);
            vp[1] = pk2(v0.z, v0.w);
            vp[2] = pk2(v1v.x, v1v.y);
            vp[3] = pk2(v1v.z, v1v.w);
#pragma unroll
            for (int i = 0; i < 4; i++) {
                float pv = Ss[ty * 4 + i][j];
                unsigned long long pp = pk2(pv, pv);
#pragma unroll
                for (int c = 0; c < 4; c++) o2[i][c] = fma2(pp, vp[c], o2[i][c]);
            }
        }
    }

    float linv[4];
#pragma unroll
    for (int i = 0; i < 4; i++) linv[i] = 1.0f / row_l[ty * 4 + i];
#pragma unroll
    for (int i = 0; i < 4; i++) {
        float ov[8];
#pragma unroll
        for (int c = 0; c < 4; c++) upk2(o2[i][c], ov[2 * c], ov[2 * c + 1]);
#pragma unroll
        for (int e = 0; e < 8; e++) ov[e] *= linv[i];
        float4* dst = (float4*)&g_att[(size_t)(q0 + ty * 4 + i) * DIMM + h * HD + tx * 8];
        dst[0] = make_float4(ov[0], ov[1], ov[2], ov[3]);
        dst[1] = make_float4(ov[4], ov[5], ov[6], ov[7]);
    }
}

// ---------------- v1 passthrough -------------------------------------------
__global__ void copy_v1(const float4* __restrict__ src, float4* __restrict__ dst, int n4) {
    int idx = blockIdx.x * blockDim.x + threadIdx.x;
    if (idx < n4) dst[idx] = src[idx];
}

// ---------------- launch ----------------------------------------------------
extern "C" void kernel_launch(void* const* d_in, const int* in_sizes, int n_in,
                              void* d_out, int out_size) {
    const float* x = (const float*)d_in[0];
    const float* v1 = (const float*)d_in[1];
    const float* Wq = (const float*)d_in[2];
    const float* Wk = (const float*)d_in[3];
    const float* Wv = (const float*)d_in[4];
    const float* Wp = (const float*)d_in[5];
    const float* lamb = (const float*)d_in[6];
    float* out = (float*)d_out;

    cudaFuncSetAttribute(qkv_mma, cudaFuncAttributeMaxDynamicSharedMemorySize, GSMEM);
    cudaFuncSetAttribute(proj_mma, cudaFuncAttributeMaxDynamicSharedMemorySize, GSMEM);
    cudaFuncSetAttribute(flash_kernel, cudaFuncAttributeMaxDynamicSharedMemorySize,
                         FLASH_SMEM);

    rope_table<<<(TT * 64 + 255) / 256, 256>>>();

    const int n4 = TT * DIMM / 4;
    cvt_kernel<<<(n4 + 255) / 256, 256>>>((const float4*)x, 0);
    cvt_kernel<<<(n4 + 255) / 256, 256>>>((const float4*)Wq, 1);
    cvt_kernel<<<(n4 + 255) / 256, 256>>>((const float4*)Wk, 2);
    cvt_kernel<<<(n4 + 255) / 256, 256>>>((const float4*)Wv, 3);
    cvt_kernel<<<(n4 + 255) / 256, 256>>>((const float4*)Wp, 4);

    dim3 gqkv(DIMM / 128, TT / 128, 3);
    qkv_mma<<<gqkv, 256, GSMEM>>>();

    post_qkv<<<TT, 256>>>(v1, lamb);

    dim3 gfl(TT / BQ, NH);
    flash_kernel<<<gfl, 256, FLASH_SMEM>>>();

    cvt_kernel<<<(n4 + 255) / 256, 256>>>((const float4*)g_att, 5);

    dim3 gproj(DIMM / 128, TT / 128);
    proj_mma<<<gproj, 256, GSMEM>>>(out);

    if (out_size >= 2 * TT * DIMM) {
        copy_v1<<<(TT * DIMM / 4 + 255) / 256, 256>>>(
            (const float4*)v1, (float4*)(out + (size_t)TT * DIMM), TT * DIMM / 4);
    }
}

// round 6
// speedup vs baseline: 2.5219x; 1.7847x over previous
#include <cuda_runtime.h>
#include <cuda_bf16.h>
#include <math.h>
#include <stdint.h>

#define TT    2048
#define DIMM  2048
#define NH    16
#define HD    128
#define EPSF  1.1920929e-07f

// ---------------- scratch (device globals: no allocation allowed) ----------
__device__ float g_q[TT * DIMM];
__device__ float g_k[TT * DIMM];
__device__ float g_v[TT * DIMM];
__device__ float g_cos[TT * 64];
__device__ float g_sin[TT * 64];

// split-precision bf16 operands
__device__ __nv_bfloat16 g_xh[TT * DIMM],    g_xl[TT * DIMM];
__device__ __nv_bfloat16 g_wqh[DIMM * DIMM], g_wql[DIMM * DIMM];
__device__ __nv_bfloat16 g_wkh[DIMM * DIMM], g_wkl[DIMM * DIMM];
__device__ __nv_bfloat16 g_wvh[DIMM * DIMM], g_wvl[DIMM * DIMM];
__device__ __nv_bfloat16 g_wph[DIMM * DIMM], g_wpl[DIMM * DIMM];
__device__ __nv_bfloat16 g_ah[TT * DIMM],    g_al[TT * DIMM];
__device__ __nv_bfloat16 g_qh[TT * DIMM],    g_ql[TT * DIMM];
__device__ __nv_bfloat16 g_kh[TT * DIMM],    g_kl[TT * DIMM];
__device__ __nv_bfloat16 g_vh[TT * DIMM],    g_vl[TT * DIMM];

// ---------------- baseline-PTX helpers -------------------------------------
__device__ __forceinline__ uint32_t smem_u32(const void* p) {
    uint32_t a;
    asm("{ .reg .u64 t; cvta.to.shared.u64 t, %1; cvt.u32.u64 %0, t; }"
        : "=r"(a) : "l"(p));
    return a;
}
__device__ __forceinline__ void cp16(uint32_t dst, const void* src) {
    asm volatile("cp.async.cg.shared.global [%0], [%1], 16;"
                 :: "r"(dst), "l"(src) : "memory");
}
__device__ __forceinline__ void cp_commit() {
    asm volatile("cp.async.commit_group;" ::: "memory");
}
__device__ __forceinline__ void cp_wait1() {
    asm volatile("cp.async.wait_group 1;" ::: "memory");
}
__device__ __forceinline__ void cp_wait0() {
    asm volatile("cp.async.wait_group 0;" ::: "memory");
}

#define LDM_X4(r0, r1, r2, r3, a)                                              \
    asm volatile("ldmatrix.sync.aligned.m8n8.x4.shared.b16 {%0,%1,%2,%3},[%4];"\
                 : "=r"(r0), "=r"(r1), "=r"(r2), "=r"(r3) : "r"(a))
#define LDM_X2(r0, r1, a)                                                      \
    asm volatile("ldmatrix.sync.aligned.m8n8.x2.shared.b16 {%0,%1},[%2];"      \
                 : "=r"(r0), "=r"(r1) : "r"(a))
#define LDM_X2T(r0, r1, a)                                                     \
    asm volatile("ldmatrix.sync.aligned.m8n8.x2.trans.shared.b16 {%0,%1},[%2];"\
                 : "=r"(r0), "=r"(r1) : "r"(a))

#define MMA_BF16(c, a, b)                                                      \
    asm volatile(                                                              \
        "mma.sync.aligned.m16n8k16.row.col.f32.bf16.bf16.f32 "                 \
        "{%0,%1,%2,%3},{%4,%5,%6,%7},{%8,%9},{%0,%1,%2,%3};"                   \
        : "+f"((c)[0]), "+f"((c)[1]), "+f"((c)[2]), "+f"((c)[3])               \
        : "r"((a)[0]), "r"((a)[1]), "r"((a)[2]), "r"((a)[3]),                  \
          "r"((b)[0]), "r"((b)[1]))

__device__ __forceinline__ uint32_t bfpack(__nv_bfloat16 a, __nv_bfloat16 b) {
    return ((uint32_t)(*(uint16_t*)&b) << 16) | (uint32_t)(*(uint16_t*)&a);
}
__device__ __forceinline__ void split2(float a, float b, uint32_t& hi, uint32_t& lo) {
    __nv_bfloat16 ha = __float2bfloat16_rn(a), hb = __float2bfloat16_rn(b);
    __nv_bfloat16 la = __float2bfloat16_rn(a - __bfloat162float(ha));
    __nv_bfloat16 lb = __float2bfloat16_rn(b - __bfloat162float(hb));
    hi = bfpack(ha, hb);
    lo = bfpack(la, lb);
}

// ---------------- fp32 -> bf16 hi/lo conversion (x, weights) ---------------
__global__ __launch_bounds__(256) void cvt_kernel(const float4* __restrict__ src,
                                                  int which) {
    __nv_bfloat16* hi;
    __nv_bfloat16* lo;
    switch (which) {
        case 0: hi = g_xh;  lo = g_xl;  break;
        case 1: hi = g_wqh; lo = g_wql; break;
        case 2: hi = g_wkh; lo = g_wkl; break;
        case 3: hi = g_wvh; lo = g_wvl; break;
        default: hi = g_wph; lo = g_wpl; break;
    }
    int i = blockIdx.x * blockDim.x + threadIdx.x;
    if (i >= TT * DIMM / 4) return;
    float4 v = src[i];
    __nv_bfloat16 h[4], l[4];
    h[0] = __float2bfloat16_rn(v.x); l[0] = __float2bfloat16_rn(v.x - __bfloat162float(h[0]));
    h[1] = __float2bfloat16_rn(v.y); l[1] = __float2bfloat16_rn(v.y - __bfloat162float(h[1]));
    h[2] = __float2bfloat16_rn(v.z); l[2] = __float2bfloat16_rn(v.z - __bfloat162float(h[2]));
    h[3] = __float2bfloat16_rn(v.w); l[3] = __float2bfloat16_rn(v.w - __bfloat162float(h[3]));
    ((uint2*)hi)[i] = *(uint2*)h;
    ((uint2*)lo)[i] = *(uint2*)l;
}

// ---------------- mma.sync GEMM: C[M,N] = A @ B^T --------------------------
#define GROW   80
#define GTILE  (128 * GROW)
#define GSTAGE (4 * GTILE)
#define GSMEM  (2 * GSTAGE)

__device__ __forceinline__ void g_load_chunk(
    uint32_t base, const __nv_bfloat16* Ah, const __nv_bfloat16* Al,
    const __nv_bfloat16* Bh, const __nv_bfloat16* Bl,
    int mBase, int nBase, int kc, int tid) {
#pragma unroll
    for (int j = 0; j < 8; j++) {
        const int t = j >> 1;
        const int rem = tid + (j & 1) * 256;
        const int r = rem >> 2;
        const int u = rem & 3;
        const __nv_bfloat16* s = (t == 0) ? Ah : (t == 1) ? Al : (t == 2) ? Bh : Bl;
        const int rb = (t < 2) ? mBase : nBase;
        cp16(base + t * GTILE + r * GROW + u * 16,
             s + (size_t)(rb + r) * DIMM + kc + u * 8);
    }
}

__device__ __forceinline__ void gemm_mma(const __nv_bfloat16* Ah, const __nv_bfloat16* Al,
                                         const __nv_bfloat16* Bh, const __nv_bfloat16* Bl,
                                         float* __restrict__ C) {
    extern __shared__ char sm[];
    const uint32_t smb = smem_u32(sm);
    const int tid = threadIdx.x;
    const int wid = tid >> 5;
    const int lane = tid & 31;
    const int mBase = blockIdx.y * 128;
    const int nBase = blockIdx.x * 128;
    const int wm = (wid >> 2) * 64;
    const int wn = (wid & 3) * 32;

    const int rowA = ((lane >> 3) & 1) * 8 + (lane & 7);
    const int colA = (lane >> 4) * 16;
    const int rowB = lane & 7;
    const int colB = ((lane >> 3) & 1) * 16;

    float acc[4][4][4];
#pragma unroll
    for (int i = 0; i < 4; i++)
#pragma unroll
        for (int n = 0; n < 4; n++)
#pragma unroll
            for (int v = 0; v < 4; v++) acc[i][n][v] = 0.0f;

    g_load_chunk(smb, Ah, Al, Bh, Bl, mBase, nBase, 0, tid);
    cp_commit();

    for (int c = 0; c < 64; c++) {
        const uint32_t cur = smb + (c & 1) * GSTAGE;
        if (c + 1 < 64) {
            g_load_chunk(smb + ((c + 1) & 1) * GSTAGE, Ah, Al, Bh, Bl,
                         mBase, nBase, (c + 1) * 32, tid);
            cp_commit();
            cp_wait1();
        } else {
            cp_wait0();
        }
        __syncthreads();

        const uint32_t Ab = cur;
        const uint32_t Alb = cur + GTILE;
        const uint32_t Bb = cur + 2 * GTILE;
        const uint32_t Blb = cur + 3 * GTILE;

#pragma unroll
        for (int s = 0; s < 2; s++) {
            uint32_t ah[4][4], al2[4][4], bh[4][2], bl[4][2];
#pragma unroll
            for (int i = 0; i < 4; i++)
                LDM_X4(ah[i][0], ah[i][1], ah[i][2], ah[i][3],
                       Ab + (wm + i * 16 + rowA) * GROW + s * 32 + colA);
#pragma unroll
            for (int n = 0; n < 4; n++)
                LDM_X2(bh[n][0], bh[n][1],
                       Bb + (wn + n * 8 + rowB) * GROW + s * 32 + colB);
#pragma unroll
            for (int i = 0; i < 4; i++)
#pragma unroll
                for (int n = 0; n < 4; n++) MMA_BF16(acc[i][n], ah[i], bh[n]);

#pragma unroll
            for (int n = 0; n < 4; n++)
                LDM_X2(bl[n][0], bl[n][1],
                       Blb + (wn + n * 8 + rowB) * GROW + s * 32 + colB);
#pragma unroll
            for (int i = 0; i < 4; i++)
#pragma unroll
                for (int n = 0; n < 4; n++) MMA_BF16(acc[i][n], ah[i], bl[n]);

#pragma unroll
            for (int i = 0; i < 4; i++)
                LDM_X4(al2[i][0], al2[i][1], al2[i][2], al2[i][3],
                       Alb + (wm + i * 16 + rowA) * GROW + s * 32 + colA);
#pragma unroll
            for (int i = 0; i < 4; i++)
#pragma unroll
                for (int n = 0; n < 4; n++) MMA_BF16(acc[i][n], al2[i], bh[n]);
        }
        __syncthreads();
    }

    const int r0 = mBase + wm + (lane >> 2);
    const int c0 = nBase + wn + (lane & 3) * 2;
#pragma unroll
    for (int i = 0; i < 4; i++)
#pragma unroll
        for (int n = 0; n < 4; n++) {
            *(float2*)&C[(size_t)(r0 + i * 16) * DIMM + c0 + n * 8] =
                make_float2(acc[i][n][0], acc[i][n][1]);
            *(float2*)&C[(size_t)(r0 + i * 16 + 8) * DIMM + c0 + n * 8] =
                make_float2(acc[i][n][2], acc[i][n][3]);
        }
}

__global__ __launch_bounds__(256) void qkv_mma() {
    if (blockIdx.z == 0)      gemm_mma(g_xh, g_xl, g_wqh, g_wql, g_q);
    else if (blockIdx.z == 1) gemm_mma(g_xh, g_xl, g_wkh, g_wkl, g_k);
    else                      gemm_mma(g_xh, g_xl, g_wvh, g_wvl, g_v);
}

__global__ __launch_bounds__(256) void proj_mma(float* __restrict__ out) {
    gemm_mma(g_ah, g_al, g_wph, g_wpl, out);
}

// ---------------- RoPE cos/sin table ---------------------------------------
__global__ void rope_table() {
    int idx = blockIdx.x * blockDim.x + threadIdx.x;
    if (idx >= TT * 64) return;
    int t = idx >> 6;
    int i = idx & 63;
    float e = (float)(2 * i) * (1.0f / 128.0f);
    float invf = 1.0f / powf(10000.0f, e);
    float fr = (float)t * invf;
    g_cos[idx] = (float)cos((double)fr);
    g_sin[idx] = (float)sin((double)fr);
}

// ------- v-mix + per-head RMS norm + RoPE, emitting bf16 hi/lo -------------
__global__ __launch_bounds__(256) void post_qkv(const float* __restrict__ v1,
                                                const float* __restrict__ lambp) {
    const int t = blockIdx.x;
    const int tid = threadIdx.x;
    const float lamb = *lambp;

    const float* vrow = g_v + (size_t)t * DIMM;
    const float* v1row = v1 + (size_t)t * DIMM;
    uint32_t* vhp = (uint32_t*)g_vh + (size_t)t * DIMM / 2;
    uint32_t* vlp = (uint32_t*)g_vl + (size_t)t * DIMM / 2;
    for (int i = tid; i < DIMM / 2; i += 256) {
        float a = (1.0f - lamb) * vrow[2 * i] + lamb * v1row[2 * i];
        float b = (1.0f - lamb) * vrow[2 * i + 1] + lamb * v1row[2 * i + 1];
        uint32_t hi, lo;
        split2(a, b, hi, lo);
        vhp[i] = hi;
        vlp[i] = lo;
    }

    const int warp = tid >> 5;
    const int lane = tid & 31;

    for (int hh = warp; hh < 2 * NH; hh += 8) {
        const int head = hh >> 1;
        const float* p = ((hh & 1) ? g_k : g_q) + (size_t)t * DIMM + head * HD;
        uint32_t* dsth = (uint32_t*)((hh & 1) ? g_kh : g_qh) +
                         ((size_t)t * DIMM + head * HD) / 2;
        uint32_t* dstl = (uint32_t*)((hh & 1) ? g_kl : g_ql) +
                         ((size_t)t * DIMM + head * HD) / 2;

        float4 f = *(const float4*)&p[lane * 4];
        float ss = f.x * f.x + f.y * f.y + f.z * f.z + f.w * f.w;
#pragma unroll
        for (int off = 16; off; off >>= 1) ss += __shfl_xor_sync(0xffffffffu, ss, off);
        float sc = rsqrtf(ss * (1.0f / 128.0f) + EPSF);
        __syncwarp();

        const int i0 = 2 * lane;  // 0..62 even
        float x1a = p[i0] * sc,     x2a = p[i0 + 64] * sc;
        float x1b = p[i0 + 1] * sc, x2b = p[i0 + 65] * sc;
        float ca = g_cos[t * 64 + i0], sa = g_sin[t * 64 + i0];
        float cb = g_cos[t * 64 + i0 + 1], sb = g_sin[t * 64 + i0 + 1];
        float y1a = x1a * ca + x2a * sa, y2a = x2a * ca - x1a * sa;
        float y1b = x1b * cb + x2b * sb, y2b = x2b * cb - x1b * sb;
        uint32_t hi, lo;
        split2(y1a, y1b, hi, lo);
        dsth[lane] = hi; dstl[lane] = lo;
        split2(y2a, y2b, hi, lo);
        dsth[lane + 32] = hi; dstl[lane + 32] = lo;
    }
}

// ---------------- flash attention via mma.sync (split bf16) ----------------
#define FROW   272                 // 128 bf16 (256B) + 16B pad
#define FTILE  (64 * FROW)         // 17408
#define FSTAGE (4 * FTILE)         // Khi, Klo, Vhi, Vlo
#define FSMEM  (2 * FSTAGE)        // 139264

__device__ __forceinline__ void f_load_stage(uint32_t base, int s0, int h, int tid) {
#pragma unroll
    for (int t = 0; t < 4; t++) {
        const __nv_bfloat16* src = (t == 0) ? g_kh : (t == 1) ? g_kl
                                 : (t == 2) ? g_vh : g_vl;
#pragma unroll
        for (int j = 0; j < 4; j++) {
            int idx = tid + j * 256;
            int r = idx >> 4, u = idx & 15;
            cp16(base + t * FTILE + r * FROW + u * 16,
                 src + (size_t)(s0 + r) * DIMM + h * HD + u * 8);
        }
    }
}

__global__ __launch_bounds__(256, 1) void flash_mma() {
    extern __shared__ char sm[];
    const uint32_t smb = smem_u32(sm);
    const int h = blockIdx.y;
    const int qb = gridDim.x - 1 - blockIdx.x;
    const int q0 = qb * 128;
    const int tid = threadIdx.x;
    const int wid = tid >> 5;
    const int lane = tid & 31;
    const int wm = wid * 16;

    // ---- Q fragments (hi/lo) from global ----
    uint32_t qh[8][4], ql[8][4];
    {
        const uint32_t* qhp = (const uint32_t*)g_qh;
        const uint32_t* qlp = (const uint32_t*)g_ql;
        const int r0 = q0 + wm + (lane >> 2);
        const int cb = h * HD + (lane & 3) * 2;
#pragma unroll
        for (int ks = 0; ks < 8; ks++) {
            uint32_t i00 = ((uint32_t)r0 * DIMM + cb + ks * 16) >> 1;
            uint32_t i10 = i00 + 8 * (DIMM / 2);
            qh[ks][0] = qhp[i00];     qh[ks][1] = qhp[i10];
            qh[ks][2] = qhp[i00 + 4]; qh[ks][3] = qhp[i10 + 4];
            ql[ks][0] = qlp[i00];     ql[ks][1] = qlp[i10];
            ql[ks][2] = qlp[i00 + 4]; ql[ks][3] = qlp[i10 + 4];
        }
    }

    float o[16][4];
#pragma unroll
    for (int n = 0; n < 16; n++)
#pragma unroll
        for (int v = 0; v < 4; v++) o[n][v] = 0.0f;
    float m[2] = {-INFINITY, -INFINITY};
    float l[2] = {0.0f, 0.0f};

    const int nkb = 2 * qb + 2;
    const float scale = 0.08838834764831845f;

    f_load_stage(smb, 0, h, tid);
    cp_commit();

    const int rowB = lane & 7;
    const int colB = ((lane >> 3) & 1) * 16;

    for (int kb = 0; kb < nkb; kb++) {
        const uint32_t cur = smb + (kb & 1) * FSTAGE;
        if (kb + 1 < nkb) {
            f_load_stage(smb + ((kb + 1) & 1) * FSTAGE, (kb + 1) * 64, h, tid);
            cp_commit();
            cp_wait1();
        } else {
            cp_wait0();
        }
        __syncthreads();

        const int s0 = kb * 64;
        const uint32_t Kh = cur;
        const uint32_t Kl = cur + FTILE;
        const uint32_t Vh = cur + 2 * FTILE;
        const uint32_t Vl = cur + 3 * FTILE;

        // ---- S = Q K^T (3-term split) ----
        float sc_[8][4];
#pragma unroll
        for (int n = 0; n < 8; n++)
#pragma unroll
            for (int v = 0; v < 4; v++) sc_[n][v] = 0.0f;

#pragma unroll
        for (int ks = 0; ks < 8; ks++) {
#pragma unroll
            for (int n = 0; n < 8; n++) {
                uint32_t bh[2], bl[2];
                LDM_X2(bh[0], bh[1], Kh + (n * 8 + rowB) * FROW + ks * 32 + colB);
                LDM_X2(bl[0], bl[1], Kl + (n * 8 + rowB) * FROW + ks * 32 + colB);
                MMA_BF16(sc_[n], qh[ks], bh);
                MMA_BF16(sc_[n], qh[ks], bl);
                MMA_BF16(sc_[n], ql[ks], bh);
            }
        }

        // ---- scale + causal mask ----
        if (s0 + 63 > q0 + wm) {
            const int r0 = q0 + wm + (lane >> 2);
#pragma unroll
            for (int n = 0; n < 8; n++) {
                int c0 = s0 + n * 8 + (lane & 3) * 2;
#pragma unroll
                for (int e = 0; e < 2; e++) {
                    sc_[n][e]     = (c0 + e <= r0)     ? sc_[n][e] * scale     : -1e30f;
                    sc_[n][e + 2] = (c0 + e <= r0 + 8) ? sc_[n][e + 2] * scale : -1e30f;
                }
            }
        } else {
#pragma unroll
            for (int n = 0; n < 8; n++)
#pragma unroll
                for (int v = 0; v < 4; v++) sc_[n][v] *= scale;
        }

        // ---- online softmax (rows r: e=0, rows r+8: e=1) ----
        float alpha[2];
#pragma unroll
        for (int e = 0; e < 2; e++) {
            float mt = m[e];
#pragma unroll
            for (int n = 0; n < 8; n++)
                mt = fmaxf(mt, fmaxf(sc_[n][2 * e], sc_[n][2 * e + 1]));
            mt = fmaxf(mt, __shfl_xor_sync(0xffffffffu, mt, 1));
            mt = fmaxf(mt, __shfl_xor_sync(0xffffffffu, mt, 2));
            alpha[e] = __expf(m[e] - mt);
            m[e] = mt;
            float sum = 0.0f;
#pragma unroll
            for (int n = 0; n < 8; n++) {
                float p0 = __expf(sc_[n][2 * e] - mt);
                float p1 = __expf(sc_[n][2 * e + 1] - mt);
                sc_[n][2 * e] = p0;
                sc_[n][2 * e + 1] = p1;
                sum += p0 + p1;
            }
            sum += __shfl_xor_sync(0xffffffffu, sum, 1);
            sum += __shfl_xor_sync(0xffffffffu, sum, 2);
            l[e] = l[e] * alpha[e] + sum;
        }
#pragma unroll
        for (int n = 0; n < 16; n++) {
            o[n][0] *= alpha[0];
            o[n][1] *= alpha[0];
            o[n][2] *= alpha[1];
            o[n][3] *= alpha[1];
        }

        // ---- P -> split bf16 A-fragments ----
        uint32_t ph[4][4], pl[4][4];
#pragma unroll
        for (int ks = 0; ks < 4; ks++) {
            split2(sc_[2 * ks][0],     sc_[2 * ks][1],     ph[ks][0], pl[ks][0]);
            split2(sc_[2 * ks][2],     sc_[2 * ks][3],     ph[ks][1], pl[ks][1]);
            split2(sc_[2 * ks + 1][0], sc_[2 * ks + 1][1], ph[ks][2], pl[ks][2]);
            split2(sc_[2 * ks + 1][2], sc_[2 * ks + 1][3], ph[ks][3], pl[ks][3]);
        }

        // ---- O += P V (3-term split), V via ldmatrix.trans ----
        const int vrow0 = ((lane >> 3) & 1) * 8 + (lane & 7);
#pragma unroll
        for (int ks = 0; ks < 4; ks++) {
#pragma unroll
            for (int n = 0; n < 16; n++) {
                uint32_t vh2[2], vl2[2];
                LDM_X2T(vh2[0], vh2[1], Vh + (ks * 16 + vrow0) * FROW + n * 16);
                LDM_X2T(vl2[0], vl2[1], Vl + (ks * 16 + vrow0) * FROW + n * 16);
                MMA_BF16(o[n], ph[ks], vh2);
                MMA_BF16(o[n], ph[ks], vl2);
                MMA_BF16(o[n], pl[ks], vh2);
            }
        }
        __syncthreads();
    }

    // ---- normalize + write hi/lo bf16 output ----
    const float linv0 = 1.0f / l[0];
    const float linv1 = 1.0f / l[1];
    uint32_t* ahp = (uint32_t*)g_ah;
    uint32_t* alp = (uint32_t*)g_al;
    const int r0 = q0 + wm + (lane >> 2);
    const int cb = h * HD + (lane & 3) * 2;
#pragma unroll
    for (int n = 0; n < 16; n++) {
        uint32_t i0 = ((uint32_t)r0 * DIMM + cb + n * 8) >> 1;
        uint32_t i1 = i0 + 8 * (DIMM / 2);
        uint32_t hi, lo;
        split2(o[n][0] * linv0, o[n][1] * linv0, hi, lo);
        ahp[i0] = hi; alp[i0] = lo;
        split2(o[n][2] * linv1, o[n][3] * linv1, hi, lo);
        ahp[i1] = hi; alp[i1] = lo;
    }
}

// ---------------- v1 passthrough -------------------------------------------
__global__ void copy_v1(const float4* __restrict__ src, float4* __restrict__ dst, int n4) {
    int idx = blockIdx.x * blockDim.x + threadIdx.x;
    if (idx < n4) dst[idx] = src[idx];
}

// ---------------- launch ----------------------------------------------------
extern "C" void kernel_launch(void* const* d_in, const int* in_sizes, int n_in,
                              void* d_out, int out_size) {
    const float* x = (const float*)d_in[0];
    const float* v1 = (const float*)d_in[1];
    const float* Wq = (const float*)d_in[2];
    const float* Wk = (const float*)d_in[3];
    const float* Wv = (const float*)d_in[4];
    const float* Wp = (const float*)d_in[5];
    const float* lamb = (const float*)d_in[6];
    float* out = (float*)d_out;

    cudaFuncSetAttribute(qkv_mma, cudaFuncAttributeMaxDynamicSharedMemorySize, GSMEM);
    cudaFuncSetAttribute(proj_mma, cudaFuncAttributeMaxDynamicSharedMemorySize, GSMEM);
    cudaFuncSetAttribute(flash_mma, cudaFuncAttributeMaxDynamicSharedMemorySize, FSMEM);

    rope_table<<<(TT * 64 + 255) / 256, 256>>>();

    const int n4 = TT * DIMM / 4;
    cvt_kernel<<<(n4 + 255) / 256, 256>>>((const float4*)x, 0);
    cvt_kernel<<<(n4 + 255) / 256, 256>>>((const float4*)Wq, 1);
    cvt_kernel<<<(n4 + 255) / 256, 256>>>((const float4*)Wk, 2);
    cvt_kernel<<<(n4 + 255) / 256, 256>>>((const float4*)Wv, 3);
    cvt_kernel<<<(n4 + 255) / 256, 256>>>((const float4*)Wp, 4);

    dim3 gqkv(DIMM / 128, TT / 128, 3);
    qkv_mma<<<gqkv, 256, GSMEM>>>();

    post_qkv<<<TT, 256>>>(v1, lamb);

    dim3 gfl(TT / 128, NH);
    flash_mma<<<gfl, 256, FSMEM>>>();

    dim3 gproj(DIMM / 128, TT / 128);
    proj_mma<<<gproj, 256, GSMEM>>>(out);

    if (out_size >= 2 * TT * DIMM) {
        copy_v1<<<(TT * DIMM / 4 + 255) / 256, 256>>>(
            (const float4*)v1, (float4*)(out + (size_t)TT * DIMM), TT * DIMM / 4);
    }
}

// round 7
// speedup vs baseline: 2.5290x; 1.0028x over previous
#include <cuda_runtime.h>
#include <cuda_bf16.h>
#include <math.h>
#include <stdint.h>

#define TT    2048
#define DIMM  2048
#define NH    16
#define HD    128
#define EPSF  1.1920929e-07f

// ---------------- scratch (device globals: no allocation allowed) ----------
__device__ float g_q[TT * DIMM];
__device__ float g_k[TT * DIMM];
__device__ float g_v[TT * DIMM];
__device__ float g_cos[TT * 64];
__device__ float g_sin[TT * 64];

// split-precision bf16 operands
__device__ __nv_bfloat16 g_xh[TT * DIMM],    g_xl[TT * DIMM];
__device__ __nv_bfloat16 g_wqh[DIMM * DIMM], g_wql[DIMM * DIMM];
__device__ __nv_bfloat16 g_wkh[DIMM * DIMM], g_wkl[DIMM * DIMM];
__device__ __nv_bfloat16 g_wvh[DIMM * DIMM], g_wvl[DIMM * DIMM];
__device__ __nv_bfloat16 g_wph[DIMM * DIMM], g_wpl[DIMM * DIMM];
__device__ __nv_bfloat16 g_ah[TT * DIMM],    g_al[TT * DIMM];
__device__ __nv_bfloat16 g_qh[TT * DIMM],    g_ql[TT * DIMM];
__device__ __nv_bfloat16 g_kh[TT * DIMM],    g_kl[TT * DIMM];
__device__ __nv_bfloat16 g_vh[TT * DIMM],    g_vl[TT * DIMM];

// ---------------- baseline-PTX helpers -------------------------------------
__device__ __forceinline__ uint32_t smem_u32(const void* p) {
    uint32_t a;
    asm("{ .reg .u64 t; cvta.to.shared.u64 t, %1; cvt.u32.u64 %0, t; }"
        : "=r"(a) : "l"(p));
    return a;
}
__device__ __forceinline__ void cp16(uint32_t dst, const void* src) {
    asm volatile("cp.async.cg.shared.global [%0], [%1], 16;"
                 :: "r"(dst), "l"(src) : "memory");
}
__device__ __forceinline__ void cp_commit() {
    asm volatile("cp.async.commit_group;" ::: "memory");
}
__device__ __forceinline__ void cp_wait1() {
    asm volatile("cp.async.wait_group 1;" ::: "memory");
}
__device__ __forceinline__ void cp_wait0() {
    asm volatile("cp.async.wait_group 0;" ::: "memory");
}

#define LDM_X4(r0, r1, r2, r3, a)                                              \
    asm volatile("ldmatrix.sync.aligned.m8n8.x4.shared.b16 {%0,%1,%2,%3},[%4];"\
                 : "=r"(r0), "=r"(r1), "=r"(r2), "=r"(r3) : "r"(a))
#define LDM_X4T(r0, r1, r2, r3, a)                                             \
    asm volatile(                                                              \
        "ldmatrix.sync.aligned.m8n8.x4.trans.shared.b16 {%0,%1,%2,%3},[%4];"   \
        : "=r"(r0), "=r"(r1), "=r"(r2), "=r"(r3) : "r"(a))

#define MMA_BF16(c, a, b)                                                      \
    asm volatile(                                                              \
        "mma.sync.aligned.m16n8k16.row.col.f32.bf16.bf16.f32 "                 \
        "{%0,%1,%2,%3},{%4,%5,%6,%7},{%8,%9},{%0,%1,%2,%3};"                   \
        : "+f"((c)[0]), "+f"((c)[1]), "+f"((c)[2]), "+f"((c)[3])               \
        : "r"((a)[0]), "r"((a)[1]), "r"((a)[2]), "r"((a)[3]),                  \
          "r"((b)[0]), "r"((b)[1]))

__device__ __forceinline__ uint32_t bfpack(__nv_bfloat16 a, __nv_bfloat16 b) {
    return ((uint32_t)(*(uint16_t*)&b) << 16) | (uint32_t)(*(uint16_t*)&a);
}
__device__ __forceinline__ void split2(float a, float b, uint32_t& hi, uint32_t& lo) {
    __nv_bfloat16 ha = __float2bfloat16_rn(a), hb = __float2bfloat16_rn(b);
    __nv_bfloat16 la = __float2bfloat16_rn(a - __bfloat162float(ha));
    __nv_bfloat16 lb = __float2bfloat16_rn(b - __bfloat162float(hb));
    hi = bfpack(ha, hb);
    lo = bfpack(la, lb);
}

// ---------------- fp32 -> bf16 hi/lo conversion (x + 4 weights, one grid) --
__global__ __launch_bounds__(256) void cvt_all(const float4* __restrict__ x,
                                               const float4* __restrict__ Wq,
                                               const float4* __restrict__ Wk,
                                               const float4* __restrict__ Wv,
                                               const float4* __restrict__ Wp) {
    const float4* src;
    __nv_bfloat16* hi;
    __nv_bfloat16* lo;
    switch (blockIdx.y) {
        case 0: src = x;  hi = g_xh;  lo = g_xl;  break;
        case 1: src = Wq; hi = g_wqh; lo = g_wql; break;
        case 2: src = Wk; hi = g_wkh; lo = g_wkl; break;
        case 3: src = Wv; hi = g_wvh; lo = g_wvl; break;
        default: src = Wp; hi = g_wph; lo = g_wpl; break;
    }
    int i = blockIdx.x * blockDim.x + threadIdx.x;
    if (i >= TT * DIMM / 4) return;
    float4 v = src[i];
    __nv_bfloat16 h[4], l[4];
    h[0] = __float2bfloat16_rn(v.x); l[0] = __float2bfloat16_rn(v.x - __bfloat162float(h[0]));
    h[1] = __float2bfloat16_rn(v.y); l[1] = __float2bfloat16_rn(v.y - __bfloat162float(h[1]));
    h[2] = __float2bfloat16_rn(v.z); l[2] = __float2bfloat16_rn(v.z - __bfloat162float(h[2]));
    h[3] = __float2bfloat16_rn(v.w); l[3] = __float2bfloat16_rn(v.w - __bfloat162float(h[3]));
    ((uint2*)hi)[i] = *(uint2*)h;
    ((uint2*)lo)[i] = *(uint2*)l;
}

// ---------------- mma.sync GEMM: C[M,N] = A @ B^T --------------------------
#define GROW   80
#define GTILE  (128 * GROW)
#define GSTAGE (4 * GTILE)
#define GSMEM  (2 * GSTAGE)

__device__ __forceinline__ void g_load_chunk(
    uint32_t base, const __nv_bfloat16* Ah, const __nv_bfloat16* Al,
    const __nv_bfloat16* Bh, const __nv_bfloat16* Bl,
    int mBase, int nBase, int kc, int tid) {
#pragma unroll
    for (int j = 0; j < 8; j++) {
        const int t = j >> 1;
        const int rem = tid + (j & 1) * 256;
        const int r = rem >> 2;
        const int u = rem & 3;
        const __nv_bfloat16* s = (t == 0) ? Ah : (t == 1) ? Al : (t == 2) ? Bh : Bl;
        const int rb = (t < 2) ? mBase : nBase;
        cp16(base + t * GTILE + r * GROW + u * 16,
             s + (size_t)(rb + r) * DIMM + kc + u * 8);
    }
}

__device__ __forceinline__ void gemm_mma(const __nv_bfloat16* Ah, const __nv_bfloat16* Al,
                                         const __nv_bfloat16* Bh, const __nv_bfloat16* Bl,
                                         float* __restrict__ C) {
    extern __shared__ char sm[];
    const uint32_t smb = smem_u32(sm);
    const int tid = threadIdx.x;
    const int wid = tid >> 5;
    const int lane = tid & 31;
    const int mBase = blockIdx.y * 128;
    const int nBase = blockIdx.x * 128;
    const int wm = (wid >> 2) * 64;
    const int wn = (wid & 3) * 32;

    const int row16 = lane & 15;          // 16-row span for x4 loads
    const int col16 = (lane >> 4) * 16;   // 16B column select

    float acc[4][4][4];
#pragma unroll
    for (int i = 0; i < 4; i++)
#pragma unroll
        for (int n = 0; n < 4; n++)
#pragma unroll
            for (int v = 0; v < 4; v++) acc[i][n][v] = 0.0f;

    g_load_chunk(smb, Ah, Al, Bh, Bl, mBase, nBase, 0, tid);
    cp_commit();

    for (int c = 0; c < 64; c++) {
        const uint32_t cur = smb + (c & 1) * GSTAGE;
        if (c + 1 < 64) {
            g_load_chunk(smb + ((c + 1) & 1) * GSTAGE, Ah, Al, Bh, Bl,
                         mBase, nBase, (c + 1) * 32, tid);
            cp_commit();
            cp_wait1();
        } else {
            cp_wait0();
        }
        __syncthreads();

        const uint32_t Ab = cur;
        const uint32_t Alb = cur + GTILE;
        const uint32_t Bb = cur + 2 * GTILE;
        const uint32_t Blb = cur + 3 * GTILE;

#pragma unroll
        for (int s = 0; s < 2; s++) {
            uint32_t ah[4][4], al2[4][4], bh[4][2], bl[4][2];
#pragma unroll
            for (int i = 0; i < 4; i++)
                LDM_X4(ah[i][0], ah[i][1], ah[i][2], ah[i][3],
                       Ab + (wm + i * 16 + row16) * GROW + s * 32 + col16);
#pragma unroll
            for (int n = 0; n < 2; n++) {
                uint32_t t0, t1, t2, t3;
                LDM_X4(t0, t1, t2, t3,
                       Bb + (wn + n * 16 + row16) * GROW + s * 32 + col16);
                bh[2 * n][0] = t0; bh[2 * n][1] = t2;
                bh[2 * n + 1][0] = t1; bh[2 * n + 1][1] = t3;
            }
#pragma unroll
            for (int i = 0; i < 4; i++)
#pragma unroll
                for (int n = 0; n < 4; n++) MMA_BF16(acc[i][n], ah[i], bh[n]);

#pragma unroll
            for (int n = 0; n < 2; n++) {
                uint32_t t0, t1, t2, t3;
                LDM_X4(t0, t1, t2, t3,
                       Blb + (wn + n * 16 + row16) * GROW + s * 32 + col16);
                bl[2 * n][0] = t0; bl[2 * n][1] = t2;
                bl[2 * n + 1][0] = t1; bl[2 * n + 1][1] = t3;
            }
#pragma unroll
            for (int i = 0; i < 4; i++)
#pragma unroll
                for (int n = 0; n < 4; n++) MMA_BF16(acc[i][n], ah[i], bl[n]);

#pragma unroll
            for (int i = 0; i < 4; i++)
                LDM_X4(al2[i][0], al2[i][1], al2[i][2], al2[i][3],
                       Alb + (wm + i * 16 + row16) * GROW + s * 32 + col16);
#pragma unroll
            for (int i = 0; i < 4; i++)
#pragma unroll
                for (int n = 0; n < 4; n++) MMA_BF16(acc[i][n], al2[i], bh[n]);
        }
        __syncthreads();
    }

    const int r0 = mBase + wm + (lane >> 2);
    const int c0 = nBase + wn + (lane & 3) * 2;
#pragma unroll
    for (int i = 0; i < 4; i++)
#pragma unroll
        for (int n = 0; n < 4; n++) {
            *(float2*)&C[(size_t)(r0 + i * 16) * DIMM + c0 + n * 8] =
                make_float2(acc[i][n][0], acc[i][n][1]);
            *(float2*)&C[(size_t)(r0 + i * 16 + 8) * DIMM + c0 + n * 8] =
                make_float2(acc[i][n][2], acc[i][n][3]);
        }
}

__global__ __launch_bounds__(256, 2) void qkv_mma() {
    if (blockIdx.z == 0)      gemm_mma(g_xh, g_xl, g_wqh, g_wql, g_q);
    else if (blockIdx.z == 1) gemm_mma(g_xh, g_xl, g_wkh, g_wkl, g_k);
    else                      gemm_mma(g_xh, g_xl, g_wvh, g_wvl, g_v);
}

__global__ __launch_bounds__(256, 2) void proj_mma(float* __restrict__ out) {
    gemm_mma(g_ah, g_al, g_wph, g_wpl, out);
}

// ---------------- RoPE cos/sin table ---------------------------------------
__global__ void rope_table() {
    int idx = blockIdx.x * blockDim.x + threadIdx.x;
    if (idx >= TT * 64) return;
    int t = idx >> 6;
    int i = idx & 63;
    float e = (float)(2 * i) * (1.0f / 128.0f);
    float invf = 1.0f / powf(10000.0f, e);
    float fr = (float)t * invf;
    g_cos[idx] = (float)cos((double)fr);
    g_sin[idx] = (float)sin((double)fr);
}

// ------- v-mix + per-head RMS norm + RoPE, emitting bf16 hi/lo -------------
__global__ __launch_bounds__(256) void post_qkv(const float* __restrict__ v1,
                                                const float* __restrict__ lambp) {
    const int t = blockIdx.x;
    const int tid = threadIdx.x;
    const float lamb = *lambp;

    const float* vrow = g_v + (size_t)t * DIMM;
    const float* v1row = v1 + (size_t)t * DIMM;
    uint32_t* vhp = (uint32_t*)g_vh + (size_t)t * DIMM / 2;
    uint32_t* vlp = (uint32_t*)g_vl + (size_t)t * DIMM / 2;
    for (int i = tid; i < DIMM / 2; i += 256) {
        float a = (1.0f - lamb) * vrow[2 * i] + lamb * v1row[2 * i];
        float b = (1.0f - lamb) * vrow[2 * i + 1] + lamb * v1row[2 * i + 1];
        uint32_t hi, lo;
        split2(a, b, hi, lo);
        vhp[i] = hi;
        vlp[i] = lo;
    }

    const int warp = tid >> 5;
    const int lane = tid & 31;

    for (int hh = warp; hh < 2 * NH; hh += 8) {
        const int head = hh >> 1;
        const float* p = ((hh & 1) ? g_k : g_q) + (size_t)t * DIMM + head * HD;
        uint32_t* dsth = (uint32_t*)((hh & 1) ? g_kh : g_qh) +
                         ((size_t)t * DIMM + head * HD) / 2;
        uint32_t* dstl = (uint32_t*)((hh & 1) ? g_kl : g_ql) +
                         ((size_t)t * DIMM + head * HD) / 2;

        float4 f = *(const float4*)&p[lane * 4];
        float ss = f.x * f.x + f.y * f.y + f.z * f.z + f.w * f.w;
#pragma unroll
        for (int off = 16; off; off >>= 1) ss += __shfl_xor_sync(0xffffffffu, ss, off);
        float sc = rsqrtf(ss * (1.0f / 128.0f) + EPSF);
        __syncwarp();

        const int i0 = 2 * lane;
        float x1a = p[i0] * sc,     x2a = p[i0 + 64] * sc;
        float x1b = p[i0 + 1] * sc, x2b = p[i0 + 65] * sc;
        float ca = g_cos[t * 64 + i0], sa = g_sin[t * 64 + i0];
        float cb = g_cos[t * 64 + i0 + 1], sb = g_sin[t * 64 + i0 + 1];
        float y1a = x1a * ca + x2a * sa, y2a = x2a * ca - x1a * sa;
        float y1b = x1b * cb + x2b * sb, y2b = x2b * cb - x1b * sb;
        uint32_t hi, lo;
        split2(y1a, y1b, hi, lo);
        dsth[lane] = hi; dstl[lane] = lo;
        split2(y2a, y2b, hi, lo);
        dsth[lane + 32] = hi; dstl[lane + 32] = lo;
    }
}

// ---------------- flash attention via mma.sync (split bf16) ----------------
#define FROW   272                 // 128 bf16 (256B) + 16B pad
#define FTILE  (64 * FROW)         // 17408
#define FSTAGE (4 * FTILE)         // Khi, Klo, Vhi, Vlo
#define FSMEM  (2 * FSTAGE)        // 139264

__device__ __forceinline__ void f_load_stage(uint32_t base, int s0, int h, int tid) {
#pragma unroll
    for (int t = 0; t < 4; t++) {
        const __nv_bfloat16* src = (t == 0) ? g_kh : (t == 1) ? g_kl
                                 : (t == 2) ? g_vh : g_vl;
#pragma unroll
        for (int j = 0; j < 4; j++) {
            int idx = tid + j * 256;
            int r = idx >> 4, u = idx & 15;
            cp16(base + t * FTILE + r * FROW + u * 16,
                 src + (size_t)(s0 + r) * DIMM + h * HD + u * 8);
        }
    }
}

__global__ __launch_bounds__(256, 1) void flash_mma() {
    extern __shared__ char sm[];
    const uint32_t smb = smem_u32(sm);
    const int h = blockIdx.y;
    const int qb = gridDim.x - 1 - blockIdx.x;
    const int q0 = qb * 128;
    const int tid = threadIdx.x;
    const int wid = tid >> 5;
    const int lane = tid & 31;
    const int wm = wid * 16;

    // ---- Q fragments (hi/lo) from global ----
    uint32_t qh[8][4], ql[8][4];
    {
        const uint32_t* qhp = (const uint32_t*)g_qh;
        const uint32_t* qlp = (const uint32_t*)g_ql;
        const int r0 = q0 + wm + (lane >> 2);
        const int cb = h * HD + (lane & 3) * 2;
#pragma unroll
        for (int ks = 0; ks < 8; ks++) {
            uint32_t i00 = ((uint32_t)r0 * DIMM + cb + ks * 16) >> 1;
            uint32_t i10 = i00 + 8 * (DIMM / 2);
            qh[ks][0] = qhp[i00];     qh[ks][1] = qhp[i10];
            qh[ks][2] = qhp[i00 + 4]; qh[ks][3] = qhp[i10 + 4];
            ql[ks][0] = qlp[i00];     ql[ks][1] = qlp[i10];
            ql[ks][2] = qlp[i00 + 4]; ql[ks][3] = qlp[i10 + 4];
        }
    }

    float o[16][4];
#pragma unroll
    for (int n = 0; n < 16; n++)
#pragma unroll
        for (int v = 0; v < 4; v++) o[n][v] = 0.0f;
    float m[2] = {-INFINITY, -INFINITY};
    float l[2] = {0.0f, 0.0f};

    const int nkb = 2 * qb + 2;
    const float scale = 0.08838834764831845f;

    f_load_stage(smb, 0, h, tid);
    cp_commit();

    const int row16 = lane & 15;
    const int col16 = (lane >> 4) * 16;

    for (int kb = 0; kb < nkb; kb++) {
        const uint32_t cur = smb + (kb & 1) * FSTAGE;
        if (kb + 1 < nkb) {
            f_load_stage(smb + ((kb + 1) & 1) * FSTAGE, (kb + 1) * 64, h, tid);
            cp_commit();
            cp_wait1();
        } else {
            cp_wait0();
        }
        __syncthreads();

        const int s0 = kb * 64;
        const uint32_t Kh = cur;
        const uint32_t Kl = cur + FTILE;
        const uint32_t Vh = cur + 2 * FTILE;
        const uint32_t Vl = cur + 3 * FTILE;

        // ---- S = Q K^T (3-term split) ----
        float sc_[8][4];
#pragma unroll
        for (int n = 0; n < 8; n++)
#pragma unroll
            for (int v = 0; v < 4; v++) sc_[n][v] = 0.0f;

#pragma unroll
        for (int ks = 0; ks < 8; ks++) {
#pragma unroll
            for (int np = 0; np < 4; np++) {
                uint32_t bh[2][2], bl[2][2];
                uint32_t t0, t1, t2, t3;
                LDM_X4(t0, t1, t2, t3,
                       Kh + (np * 16 + row16) * FROW + ks * 32 + col16);
                bh[0][0] = t0; bh[0][1] = t2; bh[1][0] = t1; bh[1][1] = t3;
                LDM_X4(t0, t1, t2, t3,
                       Kl + (np * 16 + row16) * FROW + ks * 32 + col16);
                bl[0][0] = t0; bl[0][1] = t2; bl[1][0] = t1; bl[1][1] = t3;
                MMA_BF16(sc_[2 * np], qh[ks], bh[0]);
                MMA_BF16(sc_[2 * np], qh[ks], bl[0]);
                MMA_BF16(sc_[2 * np], ql[ks], bh[0]);
                MMA_BF16(sc_[2 * np + 1], qh[ks], bh[1]);
                MMA_BF16(sc_[2 * np + 1], qh[ks], bl[1]);
                MMA_BF16(sc_[2 * np + 1], ql[ks], bh[1]);
            }
        }

        // ---- scale + causal mask ----
        if (s0 + 63 > q0 + wm) {
            const int r0 = q0 + wm + (lane >> 2);
#pragma unroll
            for (int n = 0; n < 8; n++) {
                int c0 = s0 + n * 8 + (lane & 3) * 2;
#pragma unroll
                for (int e = 0; e < 2; e++) {
                    sc_[n][e]     = (c0 + e <= r0)     ? sc_[n][e] * scale     : -1e30f;
                    sc_[n][e + 2] = (c0 + e <= r0 + 8) ? sc_[n][e + 2] * scale : -1e30f;
                }
            }
        } else {
#pragma unroll
            for (int n = 0; n < 8; n++)
#pragma unroll
                for (int v = 0; v < 4; v++) sc_[n][v] *= scale;
        }

        // ---- online softmax ----
        float alpha[2];
#pragma unroll
        for (int e = 0; e < 2; e++) {
            float mt = m[e];
#pragma unroll
            for (int n = 0; n < 8; n++)
                mt = fmaxf(mt, fmaxf(sc_[n][2 * e], sc_[n][2 * e + 1]));
            mt = fmaxf(mt, __shfl_xor_sync(0xffffffffu, mt, 1));
            mt = fmaxf(mt, __shfl_xor_sync(0xffffffffu, mt, 2));
            alpha[e] = __expf(m[e] - mt);
            m[e] = mt;
            float sum = 0.0f;
#pragma unroll
            for (int n = 0; n < 8; n++) {
                float p0 = __expf(sc_[n][2 * e] - mt);
                float p1 = __expf(sc_[n][2 * e + 1] - mt);
                sc_[n][2 * e] = p0;
                sc_[n][2 * e + 1] = p1;
                sum += p0 + p1;
            }
            sum += __shfl_xor_sync(0xffffffffu, sum, 1);
            sum += __shfl_xor_sync(0xffffffffu, sum, 2);
            l[e] = l[e] * alpha[e] + sum;
        }
#pragma unroll
        for (int n = 0; n < 16; n++) {
            o[n][0] *= alpha[0];
            o[n][1] *= alpha[0];
            o[n][2] *= alpha[1];
            o[n][3] *= alpha[1];
        }

        // ---- P -> split bf16 A-fragments ----
        uint32_t ph[4][4], pl[4][4];
#pragma unroll
        for (int ks = 0; ks < 4; ks++) {
            split2(sc_[2 * ks][0],     sc_[2 * ks][1],     ph[ks][0], pl[ks][0]);
            split2(sc_[2 * ks][2],     sc_[2 * ks][3],     ph[ks][1], pl[ks][1]);
            split2(sc_[2 * ks + 1][0], sc_[2 * ks + 1][1], ph[ks][2], pl[ks][2]);
            split2(sc_[2 * ks + 1][2], sc_[2 * ks + 1][3], ph[ks][3], pl[ks][3]);
        }

        // ---- O += P V (3-term split), V via ldmatrix.x4.trans ----
#pragma unroll
        for (int ks = 0; ks < 4; ks++) {
#pragma unroll
            for (int np = 0; np < 8; np++) {
                uint32_t vh2[2][2], vl2[2][2];
                uint32_t t0, t1, t2, t3;
                LDM_X4T(t0, t1, t2, t3,
                        Vh + (ks * 16 + row16) * FROW + np * 32 + col16);
                vh2[0][0] = t0; vh2[0][1] = t1; vh2[1][0] = t2; vh2[1][1] = t3;
                LDM_X4T(t0, t1, t2, t3,
                        Vl + (ks * 16 + row16) * FROW + np * 32 + col16);
                vl2[0][0] = t0; vl2[0][1] = t1; vl2[1][0] = t2; vl2[1][1] = t3;
                MMA_BF16(o[2 * np], ph[ks], vh2[0]);
                MMA_BF16(o[2 * np], ph[ks], vl2[0]);
                MMA_BF16(o[2 * np], pl[ks], vh2[0]);
                MMA_BF16(o[2 * np + 1], ph[ks], vh2[1]);
                MMA_BF16(o[2 * np + 1], ph[ks], vl2[1]);
                MMA_BF16(o[2 * np + 1], pl[ks], vh2[1]);
            }
        }
        __syncthreads();
    }

    // ---- normalize + write hi/lo bf16 output ----
    const float linv0 = 1.0f / l[0];
    const float linv1 = 1.0f / l[1];
    uint32_t* ahp = (uint32_t*)g_ah;
    uint32_t* alp = (uint32_t*)g_al;
    const int r0 = q0 + wm + (lane >> 2);
    const int cb = h * HD + (lane & 3) * 2;
#pragma unroll
    for (int n = 0; n < 16; n++) {
        uint32_t i0 = ((uint32_t)r0 * DIMM + cb + n * 8) >> 1;
        uint32_t i1 = i0 + 8 * (DIMM / 2);
        uint32_t hi, lo;
        split2(o[n][0] * linv0, o[n][1] * linv0, hi, lo);
        ahp[i0] = hi; alp[i0] = lo;
        split2(o[n][2] * linv1, o[n][3] * linv1, hi, lo);
        ahp[i1] = hi; alp[i1] = lo;
    }
}

// ---------------- v1 passthrough -------------------------------------------
__global__ void copy_v1(const float4* __restrict__ src, float4* __restrict__ dst, int n4) {
    int idx = blockIdx.x * blockDim.x + threadIdx.x;
    if (idx < n4) dst[idx] = src[idx];
}

// ---------------- launch ----------------------------------------------------
extern "C" void kernel_launch(void* const* d_in, const int* in_sizes, int n_in,
                              void* d_out, int out_size) {
    const float* x = (const float*)d_in[0];
    const float* v1 = (const float*)d_in[1];
    const float* Wq = (const float*)d_in[2];
    const float* Wk = (const float*)d_in[3];
    const float* Wv = (const float*)d_in[4];
    const float* Wp = (const float*)d_in[5];
    const float* lamb = (const float*)d_in[6];
    float* out = (float*)d_out;

    cudaFuncSetAttribute(qkv_mma, cudaFuncAttributeMaxDynamicSharedMemorySize, GSMEM);
    cudaFuncSetAttribute(proj_mma, cudaFuncAttributeMaxDynamicSharedMemorySize, GSMEM);
    cudaFuncSetAttribute(flash_mma, cudaFuncAttributeMaxDynamicSharedMemorySize, FSMEM);

    rope_table<<<(TT * 64 + 255) / 256, 256>>>();

    const int n4 = TT * DIMM / 4;
    dim3 gcvt((n4 + 255) / 256, 5);
    cvt_all<<<gcvt, 256>>>((const float4*)x, (const float4*)Wq, (const float4*)Wk,
                           (const float4*)Wv, (const float4*)Wp);

    dim3 gqkv(DIMM / 128, TT / 128, 3);
    qkv_mma<<<gqkv, 256, GSMEM>>>();

    post_qkv<<<TT, 256>>>(v1, lamb);

    dim3 gfl(TT / 128, NH);
    flash_mma<<<gfl, 256, FSMEM>>>();

    dim3 gproj(DIMM / 128, TT / 128);
    proj_mma<<<gproj, 256, GSMEM>>>(out);

    if (out_size >= 2 * TT * DIMM) {
        copy_v1<<<(TT * DIMM / 4 + 255) / 256, 256>>>(
            (const float4*)v1, (float4*)(out + (size_t)TT * DIMM), TT * DIMM / 4);
    }
}

// round 8
// speedup vs baseline: 2.8845x; 1.1406x over previous
#include <cuda_runtime.h>
#include <cuda_bf16.h>
#include <cuda_fp16.h>
#include <math.h>
#include <stdint.h>

#define TT    2048
#define DIMM  2048
#define NH    16
#define HD    128
#define EPSF  1.1920929e-07f

// ---------------- scratch (device globals: no allocation allowed) ----------
__device__ float g_q[TT * DIMM];
__device__ float g_k[TT * DIMM];
__device__ float g_v[TT * DIMM];
__device__ float g_cos[TT * 64];
__device__ float g_sin[TT * 64];

// bf16 split operands (score path: q,k GEMMs + flash S)
__device__ __nv_bfloat16 g_xh[TT * DIMM],    g_xl[TT * DIMM];
__device__ __nv_bfloat16 g_wqh[DIMM * DIMM], g_wql[DIMM * DIMM];
__device__ __nv_bfloat16 g_wkh[DIMM * DIMM], g_wkl[DIMM * DIMM];
__device__ __nv_bfloat16 g_qh[TT * DIMM],    g_ql[TT * DIMM];
__device__ __nv_bfloat16 g_kh[TT * DIMM],    g_kl[TT * DIMM];

// fp16 operands (linear path: v GEMM, V, attention-out, proj)
__device__ __half g_xfh[TT * DIMM],  g_xfl[TT * DIMM];
__device__ __half g_wvfh[DIMM * DIMM];
__device__ __half g_wpfh[DIMM * DIMM];
__device__ __half g_vfh[TT * DIMM];
__device__ __half g_afh[TT * DIMM],  g_afl[TT * DIMM];

// ---------------- baseline-PTX helpers -------------------------------------
__device__ __forceinline__ uint32_t smem_u32(const void* p) {
    uint32_t a;
    asm("{ .reg .u64 t; cvta.to.shared.u64 t, %1; cvt.u32.u64 %0, t; }"
        : "=r"(a) : "l"(p));
    return a;
}
__device__ __forceinline__ void cp16(uint32_t dst, const void* src) {
    asm volatile("cp.async.cg.shared.global [%0], [%1], 16;"
                 :: "r"(dst), "l"(src) : "memory");
}
__device__ __forceinline__ void cp_commit() {
    asm volatile("cp.async.commit_group;" ::: "memory");
}
__device__ __forceinline__ void cp_wait1() {
    asm volatile("cp.async.wait_group 1;" ::: "memory");
}
__device__ __forceinline__ void cp_wait0() {
    asm volatile("cp.async.wait_group 0;" ::: "memory");
}

#define LDM_X4(r0, r1, r2, r3, a)                                              \
    asm volatile("ldmatrix.sync.aligned.m8n8.x4.shared.b16 {%0,%1,%2,%3},[%4];"\
                 : "=r"(r0), "=r"(r1), "=r"(r2), "=r"(r3) : "r"(a))
#define LDM_X4T(r0, r1, r2, r3, a)                                             \
    asm volatile(                                                              \
        "ldmatrix.sync.aligned.m8n8.x4.trans.shared.b16 {%0,%1,%2,%3},[%4];"   \
        : "=r"(r0), "=r"(r1), "=r"(r2), "=r"(r3) : "r"(a))

#define MMA_BF16(c, a, b)                                                      \
    asm volatile(                                                              \
        "mma.sync.aligned.m16n8k16.row.col.f32.bf16.bf16.f32 "                 \
        "{%0,%1,%2,%3},{%4,%5,%6,%7},{%8,%9},{%0,%1,%2,%3};"                   \
        : "+f"((c)[0]), "+f"((c)[1]), "+f"((c)[2]), "+f"((c)[3])               \
        : "r"((a)[0]), "r"((a)[1]), "r"((a)[2]), "r"((a)[3]),                  \
          "r"((b)[0]), "r"((b)[1]))
#define MMA_FP16(c, a, b)                                                      \
    asm volatile(                                                              \
        "mma.sync.aligned.m16n8k16.row.col.f32.f16.f16.f32 "                   \
        "{%0,%1,%2,%3},{%4,%5,%6,%7},{%8,%9},{%0,%1,%2,%3};"                   \
        : "+f"((c)[0]), "+f"((c)[1]), "+f"((c)[2]), "+f"((c)[3])               \
        : "r"((a)[0]), "r"((a)[1]), "r"((a)[2]), "r"((a)[3]),                  \
          "r"((b)[0]), "r"((b)[1]))

__device__ __forceinline__ uint32_t pack16(uint16_t a, uint16_t b) {
    return ((uint32_t)b << 16) | (uint32_t)a;
}
__device__ __forceinline__ void split2(float a, float b, uint32_t& hi, uint32_t& lo) {
    __nv_bfloat16 ha = __float2bfloat16_rn(a), hb = __float2bfloat16_rn(b);
    __nv_bfloat16 la = __float2bfloat16_rn(a - __bfloat162float(ha));
    __nv_bfloat16 lb = __float2bfloat16_rn(b - __bfloat162float(hb));
    hi = pack16(*(uint16_t*)&ha, *(uint16_t*)&hb);
    lo = pack16(*(uint16_t*)&la, *(uint16_t*)&lb);
}
__device__ __forceinline__ void split2h(float a, float b, uint32_t& hi, uint32_t& lo) {
    __half ha = __float2half_rn(a), hb = __float2half_rn(b);
    __half la = __float2half_rn(a - __half2float(ha));
    __half lb = __float2half_rn(b - __half2float(hb));
    hi = pack16(*(uint16_t*)&ha, *(uint16_t*)&hb);
    lo = pack16(*(uint16_t*)&la, *(uint16_t*)&lb);
}

// ---------------- conversions (one grid, y selects tensor) -----------------
// y=0: x -> bf16 hi/lo + fp16 hi/lo; y=1: Wq bf16; y=2: Wk bf16;
// y=3: Wv fp16 hi; y=4: Wp fp16 hi
__global__ __launch_bounds__(256) void cvt_all(const float4* __restrict__ x,
                                               const float4* __restrict__ Wq,
                                               const float4* __restrict__ Wk,
                                               const float4* __restrict__ Wv,
                                               const float4* __restrict__ Wp) {
    int i = blockIdx.x * blockDim.x + threadIdx.x;
    if (i >= TT * DIMM / 4) return;
    const int y = blockIdx.y;
    if (y == 0) {
        float4 v = x[i];
        __nv_bfloat16 h[4], l[4];
        __half fh[4], fl[4];
#pragma unroll
        for (int e = 0; e < 4; e++) {
            float f = (&v.x)[e];
            h[e] = __float2bfloat16_rn(f);
            l[e] = __float2bfloat16_rn(f - __bfloat162float(h[e]));
            fh[e] = __float2half_rn(f);
            fl[e] = __float2half_rn(f - __half2float(fh[e]));
        }
        ((uint2*)g_xh)[i] = *(uint2*)h;
        ((uint2*)g_xl)[i] = *(uint2*)l;
        ((uint2*)g_xfh)[i] = *(uint2*)fh;
        ((uint2*)g_xfl)[i] = *(uint2*)fl;
    } else if (y == 1 || y == 2) {
        float4 v = (y == 1) ? Wq[i] : Wk[i];
        __nv_bfloat16* hi = (y == 1) ? g_wqh : g_wkh;
        __nv_bfloat16* lo = (y == 1) ? g_wql : g_wkl;
        __nv_bfloat16 h[4], l[4];
#pragma unroll
        for (int e = 0; e < 4; e++) {
            float f = (&v.x)[e];
            h[e] = __float2bfloat16_rn(f);
            l[e] = __float2bfloat16_rn(f - __bfloat162float(h[e]));
        }
        ((uint2*)hi)[i] = *(uint2*)h;
        ((uint2*)lo)[i] = *(uint2*)l;
    } else {
        float4 v = (y == 3) ? Wv[i] : Wp[i];
        __half* hi = (y == 3) ? g_wvfh : g_wpfh;
        __half fh[4];
#pragma unroll
        for (int e = 0; e < 4; e++) fh[e] = __float2half_rn((&v.x)[e]);
        ((uint2*)hi)[i] = *(uint2*)fh;
    }
}

// ---------------- 3-term bf16 GEMM: C = A @ B^T ----------------------------
#define GROW   80
#define GTILE  (128 * GROW)
#define GSTAGE (4 * GTILE)
#define GSMEM  (2 * GSTAGE)

__device__ __forceinline__ void g_load_chunk(
    uint32_t base, const __nv_bfloat16* Ah, const __nv_bfloat16* Al,
    const __nv_bfloat16* Bh, const __nv_bfloat16* Bl,
    int mBase, int nBase, int kc, int tid) {
#pragma unroll
    for (int j = 0; j < 8; j++) {
        const int t = j >> 1;
        const int rem = tid + (j & 1) * 256;
        const int r = rem >> 2;
        const int u = rem & 3;
        const __nv_bfloat16* s = (t == 0) ? Ah : (t == 1) ? Al : (t == 2) ? Bh : Bl;
        const int rb = (t < 2) ? mBase : nBase;
        cp16(base + t * GTILE + r * GROW + u * 16,
             s + (size_t)(rb + r) * DIMM + kc + u * 16 / 2);
    }
}

__device__ __forceinline__ void gemm_mma(const __nv_bfloat16* Ah, const __nv_bfloat16* Al,
                                         const __nv_bfloat16* Bh, const __nv_bfloat16* Bl,
                                         float* __restrict__ C) {
    extern __shared__ char sm[];
    const uint32_t smb = smem_u32(sm);
    const int tid = threadIdx.x;
    const int wid = tid >> 5;
    const int lane = tid & 31;
    const int mBase = blockIdx.y * 128;
    const int nBase = blockIdx.x * 128;
    const int wm = (wid >> 2) * 64;
    const int wn = (wid & 3) * 32;

    const int row16 = lane & 15;
    const int col16 = (lane >> 4) * 16;

    float acc[4][4][4];
#pragma unroll
    for (int i = 0; i < 4; i++)
#pragma unroll
        for (int n = 0; n < 4; n++)
#pragma unroll
            for (int v = 0; v < 4; v++) acc[i][n][v] = 0.0f;

    g_load_chunk(smb, Ah, Al, Bh, Bl, mBase, nBase, 0, tid);
    cp_commit();

    for (int c = 0; c < 64; c++) {
        const uint32_t cur = smb + (c & 1) * GSTAGE;
        if (c + 1 < 64) {
            g_load_chunk(smb + ((c + 1) & 1) * GSTAGE, Ah, Al, Bh, Bl,
                         mBase, nBase, (c + 1) * 32, tid);
            cp_commit();
            cp_wait1();
        } else {
            cp_wait0();
        }
        __syncthreads();

        const uint32_t Ab = cur;
        const uint32_t Alb = cur + GTILE;
        const uint32_t Bb = cur + 2 * GTILE;
        const uint32_t Blb = cur + 3 * GTILE;

#pragma unroll
        for (int s = 0; s < 2; s++) {
            uint32_t ah[4][4], al2[4][4], bh[4][2], bl[4][2];
#pragma unroll
            for (int i = 0; i < 4; i++)
                LDM_X4(ah[i][0], ah[i][1], ah[i][2], ah[i][3],
                       Ab + (wm + i * 16 + row16) * GROW + s * 32 + col16);
#pragma unroll
            for (int n = 0; n < 2; n++) {
                uint32_t t0, t1, t2, t3;
                LDM_X4(t0, t1, t2, t3,
                       Bb + (wn + n * 16 + row16) * GROW + s * 32 + col16);
                bh[2 * n][0] = t0; bh[2 * n][1] = t2;
                bh[2 * n + 1][0] = t1; bh[2 * n + 1][1] = t3;
            }
#pragma unroll
            for (int i = 0; i < 4; i++)
#pragma unroll
                for (int n = 0; n < 4; n++) MMA_BF16(acc[i][n], ah[i], bh[n]);

#pragma unroll
            for (int n = 0; n < 2; n++) {
                uint32_t t0, t1, t2, t3;
                LDM_X4(t0, t1, t2, t3,
                       Blb + (wn + n * 16 + row16) * GROW + s * 32 + col16);
                bl[2 * n][0] = t0; bl[2 * n][1] = t2;
                bl[2 * n + 1][0] = t1; bl[2 * n + 1][1] = t3;
            }
#pragma unroll
            for (int i = 0; i < 4; i++)
#pragma unroll
                for (int n = 0; n < 4; n++) MMA_BF16(acc[i][n], ah[i], bl[n]);

#pragma unroll
            for (int i = 0; i < 4; i++)
                LDM_X4(al2[i][0], al2[i][1], al2[i][2], al2[i][3],
                       Alb + (wm + i * 16 + row16) * GROW + s * 32 + col16);
#pragma unroll
            for (int i = 0; i < 4; i++)
#pragma unroll
                for (int n = 0; n < 4; n++) MMA_BF16(acc[i][n], al2[i], bh[n]);
        }
        __syncthreads();
    }

    const int r0 = mBase + wm + (lane >> 2);
    const int c0 = nBase + wn + (lane & 3) * 2;
#pragma unroll
    for (int i = 0; i < 4; i++)
#pragma unroll
        for (int n = 0; n < 4; n++) {
            *(float2*)&C[(size_t)(r0 + i * 16) * DIMM + c0 + n * 8] =
                make_float2(acc[i][n][0], acc[i][n][1]);
            *(float2*)&C[(size_t)(r0 + i * 16 + 8) * DIMM + c0 + n * 8] =
                make_float2(acc[i][n][2], acc[i][n][3]);
        }
}

__global__ __launch_bounds__(256, 2) void qkv_mma() {
    if (blockIdx.z == 0) gemm_mma(g_xh, g_xl, g_wqh, g_wql, g_q);
    else                 gemm_mma(g_xh, g_xl, g_wkh, g_wkl, g_k);
}

// ---------------- 2-term fp16 GEMM: C = (Ah+Al) @ Bh^T ---------------------
#define G2STAGE (3 * GTILE)
#define G2SMEM  (2 * G2STAGE)

__device__ __forceinline__ void g2_load_chunk(
    uint32_t base, const __half* Ah, const __half* Al, const __half* Bh,
    int mBase, int nBase, int kc, int tid) {
#pragma unroll
    for (int j = 0; j < 6; j++) {
        const int t = j >> 1;
        const int rem = tid + (j & 1) * 256;
        const int r = rem >> 2;
        const int u = rem & 3;
        const __half* s = (t == 0) ? Ah : (t == 1) ? Al : Bh;
        const int rb = (t < 2) ? mBase : nBase;
        cp16(base + t * GTILE + r * GROW + u * 16,
             s + (size_t)(rb + r) * DIMM + kc + u * 8);
    }
}

__device__ __forceinline__ void gemm2_mma(const __half* Ah, const __half* Al,
                                          const __half* Bh, float* __restrict__ C) {
    extern __shared__ char sm[];
    const uint32_t smb = smem_u32(sm);
    const int tid = threadIdx.x;
    const int wid = tid >> 5;
    const int lane = tid & 31;
    const int mBase = blockIdx.y * 128;
    const int nBase = blockIdx.x * 128;
    const int wm = (wid >> 2) * 64;
    const int wn = (wid & 3) * 32;

    const int row16 = lane & 15;
    const int col16 = (lane >> 4) * 16;

    float acc[4][4][4];
#pragma unroll
    for (int i = 0; i < 4; i++)
#pragma unroll
        for (int n = 0; n < 4; n++)
#pragma unroll
            for (int v = 0; v < 4; v++) acc[i][n][v] = 0.0f;

    g2_load_chunk(smb, Ah, Al, Bh, mBase, nBase, 0, tid);
    cp_commit();

    for (int c = 0; c < 64; c++) {
        const uint32_t cur = smb + (c & 1) * G2STAGE;
        if (c + 1 < 64) {
            g2_load_chunk(smb + ((c + 1) & 1) * G2STAGE, Ah, Al, Bh,
                          mBase, nBase, (c + 1) * 32, tid);
            cp_commit();
            cp_wait1();
        } else {
            cp_wait0();
        }
        __syncthreads();

        const uint32_t Ab = cur;
        const uint32_t Alb = cur + GTILE;
        const uint32_t Bb = cur + 2 * GTILE;

#pragma unroll
        for (int s = 0; s < 2; s++) {
            uint32_t ah[4][4], al2[4][4], bh[4][2];
#pragma unroll
            for (int i = 0; i < 4; i++)
                LDM_X4(ah[i][0], ah[i][1], ah[i][2], ah[i][3],
                       Ab + (wm + i * 16 + row16) * GROW + s * 32 + col16);
#pragma unroll
            for (int n = 0; n < 2; n++) {
                uint32_t t0, t1, t2, t3;
                LDM_X4(t0, t1, t2, t3,
                       Bb + (wn + n * 16 + row16) * GROW + s * 32 + col16);
                bh[2 * n][0] = t0; bh[2 * n][1] = t2;
                bh[2 * n + 1][0] = t1; bh[2 * n + 1][1] = t3;
            }
#pragma unroll
            for (int i = 0; i < 4; i++)
#pragma unroll
                for (int n = 0; n < 4; n++) MMA_FP16(acc[i][n], ah[i], bh[n]);

#pragma unroll
            for (int i = 0; i < 4; i++)
                LDM_X4(al2[i][0], al2[i][1], al2[i][2], al2[i][3],
                       Alb + (wm + i * 16 + row16) * GROW + s * 32 + col16);
#pragma unroll
            for (int i = 0; i < 4; i++)
#pragma unroll
                for (int n = 0; n < 4; n++) MMA_FP16(acc[i][n], al2[i], bh[n]);
        }
        __syncthreads();
    }

    const int r0 = mBase + wm + (lane >> 2);
    const int c0 = nBase + wn + (lane & 3) * 2;
#pragma unroll
    for (int i = 0; i < 4; i++)
#pragma unroll
        for (int n = 0; n < 4; n++) {
            *(float2*)&C[(size_t)(r0 + i * 16) * DIMM + c0 + n * 8] =
                make_float2(acc[i][n][0], acc[i][n][1]);
            *(float2*)&C[(size_t)(r0 + i * 16 + 8) * DIMM + c0 + n * 8] =
                make_float2(acc[i][n][2], acc[i][n][3]);
        }
}

__global__ __launch_bounds__(256, 2) void v_mma() {
    gemm2_mma(g_xfh, g_xfl, g_wvfh, g_v);
}
__global__ __launch_bounds__(256, 2) void proj_mma(float* __restrict__ out) {
    gemm2_mma(g_afh, g_afl, g_wpfh, out);
}

// ---------------- RoPE cos/sin table ---------------------------------------
__global__ void rope_table() {
    int idx = blockIdx.x * blockDim.x + threadIdx.x;
    if (idx >= TT * 64) return;
    int t = idx >> 6;
    int i = idx & 63;
    float e = (float)(2 * i) * (1.0f / 128.0f);
    float invf = 1.0f / powf(10000.0f, e);
    float fr = (float)t * invf;
    g_cos[idx] = (float)cos((double)fr);
    g_sin[idx] = (float)sin((double)fr);
}

// ------- v-mix (-> fp16) + per-head RMS norm + RoPE (-> bf16 hi/lo) --------
__global__ __launch_bounds__(256) void post_qkv(const float* __restrict__ v1,
                                                const float* __restrict__ lambp) {
    const int t = blockIdx.x;
    const int tid = threadIdx.x;
    const float lamb = *lambp;

    const float* vrow = g_v + (size_t)t * DIMM;
    const float* v1row = v1 + (size_t)t * DIMM;
    uint32_t* vhp = (uint32_t*)g_vfh + (size_t)t * DIMM / 2;
    for (int i = tid; i < DIMM / 2; i += 256) {
        float a = (1.0f - lamb) * vrow[2 * i] + lamb * v1row[2 * i];
        float b = (1.0f - lamb) * vrow[2 * i + 1] + lamb * v1row[2 * i + 1];
        __half ha = __float2half_rn(a), hb = __float2half_rn(b);
        vhp[i] = pack16(*(uint16_t*)&ha, *(uint16_t*)&hb);
    }

    const int warp = tid >> 5;
    const int lane = tid & 31;

    for (int hh = warp; hh < 2 * NH; hh += 8) {
        const int head = hh >> 1;
        const float* p = ((hh & 1) ? g_k : g_q) + (size_t)t * DIMM + head * HD;
        uint32_t* dsth = (uint32_t*)((hh & 1) ? g_kh : g_qh) +
                         ((size_t)t * DIMM + head * HD) / 2;
        uint32_t* dstl = (uint32_t*)((hh & 1) ? g_kl : g_ql) +
                         ((size_t)t * DIMM + head * HD) / 2;

        float4 f = *(const float4*)&p[lane * 4];
        float ss = f.x * f.x + f.y * f.y + f.z * f.z + f.w * f.w;
#pragma unroll
        for (int off = 16; off; off >>= 1) ss += __shfl_xor_sync(0xffffffffu, ss, off);
        float sc = rsqrtf(ss * (1.0f / 128.0f) + EPSF);
        __syncwarp();

        const int i0 = 2 * lane;
        float x1a = p[i0] * sc,     x2a = p[i0 + 64] * sc;
        float x1b = p[i0 + 1] * sc, x2b = p[i0 + 65] * sc;
        float ca = g_cos[t * 64 + i0], sa = g_sin[t * 64 + i0];
        float cb = g_cos[t * 64 + i0 + 1], sb = g_sin[t * 64 + i0 + 1];
        float y1a = x1a * ca + x2a * sa, y2a = x2a * ca - x1a * sa;
        float y1b = x1b * cb + x2b * sb, y2b = x2b * cb - x1b * sb;
        uint32_t hi, lo;
        split2(y1a, y1b, hi, lo);
        dsth[lane] = hi; dstl[lane] = lo;
        split2(y2a, y2b, hi, lo);
        dsth[lane + 32] = hi; dstl[lane + 32] = lo;
    }
}

// ---------------- flash attention (S: bf16 3-term, PV: fp16 2-term) --------
#define FROW   272
#define FTILE  (64 * FROW)
#define FSTAGE (3 * FTILE)         // Khi, Klo (bf16), Vh (fp16)
#define FSMEM  (2 * FSTAGE)

__device__ __forceinline__ void f_load_stage(uint32_t base, int s0, int h, int tid) {
#pragma unroll
    for (int t = 0; t < 3; t++) {
        const void* srcbase = (t == 0) ? (const void*)g_kh
                            : (t == 1) ? (const void*)g_kl : (const void*)g_vfh;
#pragma unroll
        for (int j = 0; j < 4; j++) {
            int idx = tid + j * 256;
            int r = idx >> 4, u = idx & 15;
            cp16(base + t * FTILE + r * FROW + u * 16,
                 (const __half*)srcbase + (size_t)(s0 + r) * DIMM + h * HD + u * 8);
        }
    }
}

__global__ __launch_bounds__(256, 1) void flash_mma() {
    extern __shared__ char sm[];
    const uint32_t smb = smem_u32(sm);
    const int h = blockIdx.y;
    const int qb = gridDim.x - 1 - blockIdx.x;
    const int q0 = qb * 128;
    const int tid = threadIdx.x;
    const int wid = tid >> 5;
    const int lane = tid & 31;
    const int wm = wid * 16;

    uint32_t qh[8][4], ql[8][4];
    {
        const uint32_t* qhp = (const uint32_t*)g_qh;
        const uint32_t* qlp = (const uint32_t*)g_ql;
        const int r0 = q0 + wm + (lane >> 2);
        const int cb = h * HD + (lane & 3) * 2;
#pragma unroll
        for (int ks = 0; ks < 8; ks++) {
            uint32_t i00 = ((uint32_t)r0 * DIMM + cb + ks * 16) >> 1;
            uint32_t i10 = i00 + 8 * (DIMM / 2);
            qh[ks][0] = qhp[i00];     qh[ks][1] = qhp[i10];
            qh[ks][2] = qhp[i00 + 4]; qh[ks][3] = qhp[i10 + 4];
            ql[ks][0] = qlp[i00];     ql[ks][1] = qlp[i10];
            ql[ks][2] = qlp[i00 + 4]; ql[ks][3] = qlp[i10 + 4];
        }
    }

    float o[16][4];
#pragma unroll
    for (int n = 0; n < 16; n++)
#pragma unroll
        for (int v = 0; v < 4; v++) o[n][v] = 0.0f;
    float m[2] = {-INFINITY, -INFINITY};
    float l[2] = {0.0f, 0.0f};

    const int nkb = 2 * qb + 2;
    // scale * log2(e): softmax in base-2
    const float scale2 = 0.08838834764831845f * 1.4426950408889634f;

    f_load_stage(smb, 0, h, tid);
    cp_commit();

    const int row16 = lane & 15;
    const int col16 = (lane >> 4) * 16;

    for (int kb = 0; kb < nkb; kb++) {
        const uint32_t cur = smb + (kb & 1) * FSTAGE;
        if (kb + 1 < nkb) {
            f_load_stage(smb + ((kb + 1) & 1) * FSTAGE, (kb + 1) * 64, h, tid);
            cp_commit();
            cp_wait1();
        } else {
            cp_wait0();
        }
        __syncthreads();

        const int s0 = kb * 64;
        const uint32_t Kh = cur;
        const uint32_t Kl = cur + FTILE;
        const uint32_t Vh = cur + 2 * FTILE;

        float sc_[8][4];
#pragma unroll
        for (int n = 0; n < 8; n++)
#pragma unroll
            for (int v = 0; v < 4; v++) sc_[n][v] = 0.0f;

#pragma unroll
        for (int ks = 0; ks < 8; ks++) {
#pragma unroll
            for (int np = 0; np < 4; np++) {
                uint32_t bh[2][2], bl[2][2];
                uint32_t t0, t1, t2, t3;
                LDM_X4(t0, t1, t2, t3,
                       Kh + (np * 16 + row16) * FROW + ks * 32 + col16);
                bh[0][0] = t0; bh[0][1] = t2; bh[1][0] = t1; bh[1][1] = t3;
                LDM_X4(t0, t1, t2, t3,
                       Kl + (np * 16 + row16) * FROW + ks * 32 + col16);
                bl[0][0] = t0; bl[0][1] = t2; bl[1][0] = t1; bl[1][1] = t3;
                MMA_BF16(sc_[2 * np], qh[ks], bh[0]);
                MMA_BF16(sc_[2 * np], qh[ks], bl[0]);
                MMA_BF16(sc_[2 * np], ql[ks], bh[0]);
                MMA_BF16(sc_[2 * np + 1], qh[ks], bh[1]);
                MMA_BF16(sc_[2 * np + 1], qh[ks], bl[1]);
                MMA_BF16(sc_[2 * np + 1], ql[ks], bh[1]);
            }
        }

        if (s0 + 63 > q0 + wm) {
            const int r0 = q0 + wm + (lane >> 2);
#pragma unroll
            for (int n = 0; n < 8; n++) {
                int c0 = s0 + n * 8 + (lane & 3) * 2;
#pragma unroll
                for (int e = 0; e < 2; e++) {
                    sc_[n][e]     = (c0 + e <= r0)     ? sc_[n][e] * scale2     : -1e30f;
                    sc_[n][e + 2] = (c0 + e <= r0 + 8) ? sc_[n][e + 2] * scale2 : -1e30f;
                }
            }
        } else {
#pragma unroll
            for (int n = 0; n < 8; n++)
#pragma unroll
                for (int v = 0; v < 4; v++) sc_[n][v] *= scale2;
        }

        float alpha[2];
#pragma unroll
        for (int e = 0; e < 2; e++) {
            float mt = m[e];
#pragma unroll
            for (int n = 0; n < 8; n++)
                mt = fmaxf(mt, fmaxf(sc_[n][2 * e], sc_[n][2 * e + 1]));
            mt = fmaxf(mt, __shfl_xor_sync(0xffffffffu, mt, 1));
            mt = fmaxf(mt, __shfl_xor_sync(0xffffffffu, mt, 2));
            alpha[e] = exp2f(m[e] - mt);
            m[e] = mt;
            float sum = 0.0f;
#pragma unroll
            for (int n = 0; n < 8; n++) {
                float p0 = exp2f(sc_[n][2 * e] - mt);
                float p1 = exp2f(sc_[n][2 * e + 1] - mt);
                sc_[n][2 * e] = p0;
                sc_[n][2 * e + 1] = p1;
                sum += p0 + p1;
            }
            sum += __shfl_xor_sync(0xffffffffu, sum, 1);
            sum += __shfl_xor_sync(0xffffffffu, sum, 2);
            l[e] = l[e] * alpha[e] + sum;
        }
#pragma unroll
        for (int n = 0; n < 16; n++) {
            o[n][0] *= alpha[0];
            o[n][1] *= alpha[0];
            o[n][2] *= alpha[1];
            o[n][3] *= alpha[1];
        }

        // P -> fp16 hi/lo A-fragments
        uint32_t ph[4][4], pl[4][4];
#pragma unroll
        for (int ks = 0; ks < 4; ks++) {
            split2h(sc_[2 * ks][0],     sc_[2 * ks][1],     ph[ks][0], pl[ks][0]);
            split2h(sc_[2 * ks][2],     sc_[2 * ks][3],     ph[ks][1], pl[ks][1]);
            split2h(sc_[2 * ks + 1][0], sc_[2 * ks + 1][1], ph[ks][2], pl[ks][2]);
            split2h(sc_[2 * ks + 1][2], sc_[2 * ks + 1][3], ph[ks][3], pl[ks][3]);
        }

        // O += (Ph+Pl) @ Vh  (fp16, 2 terms)
#pragma unroll
        for (int ks = 0; ks < 4; ks++) {
#pragma unroll
            for (int np = 0; np < 8; np++) {
                uint32_t v2[2][2];
                uint32_t t0, t1, t2, t3;
                LDM_X4T(t0, t1, t2, t3,
                        Vh + (ks * 16 + row16) * FROW + np * 32 + col16);
                v2[0][0] = t0; v2[0][1] = t1; v2[1][0] = t2; v2[1][1] = t3;
                MMA_FP16(o[2 * np], ph[ks], v2[0]);
                MMA_FP16(o[2 * np], pl[ks], v2[0]);
                MMA_FP16(o[2 * np + 1], ph[ks], v2[1]);
                MMA_FP16(o[2 * np + 1], pl[ks], v2[1]);
            }
        }
        __syncthreads();
    }

    // normalize + write fp16 hi/lo attention output
    const float linv0 = 1.0f / l[0];
    const float linv1 = 1.0f / l[1];
    uint32_t* ahp = (uint32_t*)g_afh;
    uint32_t* alp = (uint32_t*)g_afl;
    const int r0 = q0 + wm + (lane >> 2);
    const int cb = h * HD + (lane & 3) * 2;
#pragma unroll
    for (int n = 0; n < 16; n++) {
        uint32_t i0 = ((uint32_t)r0 * DIMM + cb + n * 8) >> 1;
        uint32_t i1 = i0 + 8 * (DIMM / 2);
        uint32_t hi, lo;
        split2h(o[n][0] * linv0, o[n][1] * linv0, hi, lo);
        ahp[i0] = hi; alp[i0] = lo;
        split2h(o[n][2] * linv1, o[n][3] * linv1, hi, lo);
        ahp[i1] = hi; alp[i1] = lo;
    }
}

// ---------------- v1 passthrough -------------------------------------------
__global__ void copy_v1(const float4* __restrict__ src, float4* __restrict__ dst, int n4) {
    int idx = blockIdx.x * blockDim.x + threadIdx.x;
    if (idx < n4) dst[idx] = src[idx];
}

// ---------------- launch ----------------------------------------------------
extern "C" void kernel_launch(void* const* d_in, const int* in_sizes, int n_in,
                              void* d_out, int out_size) {
    const float* x = (const float*)d_in[0];
    const float* v1 = (const float*)d_in[1];
    const float* Wq = (const float*)d_in[2];
    const float* Wk = (const float*)d_in[3];
    const float* Wv = (const float*)d_in[4];
    const float* Wp = (const float*)d_in[5];
    const float* lamb = (const float*)d_in[6];
    float* out = (float*)d_out;

    cudaFuncSetAttribute(qkv_mma, cudaFuncAttributeMaxDynamicSharedMemorySize, GSMEM);
    cudaFuncSetAttribute(v_mma, cudaFuncAttributeMaxDynamicSharedMemorySize, G2SMEM);
    cudaFuncSetAttribute(proj_mma, cudaFuncAttributeMaxDynamicSharedMemorySize, G2SMEM);
    cudaFuncSetAttribute(flash_mma, cudaFuncAttributeMaxDynamicSharedMemorySize, FSMEM);

    rope_table<<<(TT * 64 + 255) / 256, 256>>>();

    const int n4 = TT * DIMM / 4;
    dim3 gcvt((n4 + 255) / 256, 5);
    cvt_all<<<gcvt, 256>>>((const float4*)x, (const float4*)Wq, (const float4*)Wk,
                           (const float4*)Wv, (const float4*)Wp);

    dim3 gqkv(DIMM / 128, TT / 128, 2);
    qkv_mma<<<gqkv, 256, GSMEM>>>();
    dim3 gv(DIMM / 128, TT / 128);
    v_mma<<<gv, 256, G2SMEM>>>();

    post_qkv<<<TT, 256>>>(v1, lamb);

    dim3 gfl(TT / 128, NH);
    flash_mma<<<gfl, 256, FSMEM>>>();

    dim3 gproj(DIMM / 128, TT / 128);
    proj_mma<<<gproj, 256, G2SMEM>>>(out);

    if (out_size >= 2 * TT * DIMM) {
        copy_v1<<<(TT * DIMM / 4 + 255) / 256, 256>>>(
            (const float4*)v1, (float4*)(out + (size_t)TT * DIMM), TT * DIMM / 4);
    }
}

// round 9
// speedup vs baseline: 3.7856x; 1.3124x over previous
#include <cuda_runtime.h>
#include <cuda_fp16.h>
#include <math.h>
#include <stdint.h>

#define TT    2048
#define DIMM  2048
#define NH    16
#define HD    128
#define EPSF  1.1920929e-07f

// ---------------- scratch (device globals: no allocation allowed) ----------
__device__ float g_q[TT * DIMM];
__device__ float g_k[TT * DIMM];
__device__ float g_v[TT * DIMM];
__device__ float g_cos[TT * 64];
__device__ float g_sin[TT * 64];

// fp16 operands (everything is fp16 2-term now)
__device__ __half g_xfh[TT * DIMM],  g_xfl[TT * DIMM];
__device__ __half g_wqfh[DIMM * DIMM];
__device__ __half g_wkfh[DIMM * DIMM];
__device__ __half g_wvfh[DIMM * DIMM];
__device__ __half g_wpfh[DIMM * DIMM];
__device__ __half g_qfh[TT * DIMM],  g_qfl[TT * DIMM];
__device__ __half g_kfh[TT * DIMM];
__device__ __half g_vfh[TT * DIMM];
__device__ __half g_afh[TT * DIMM],  g_afl[TT * DIMM];

// ---------------- baseline-PTX helpers -------------------------------------
__device__ __forceinline__ uint32_t smem_u32(const void* p) {
    uint32_t a;
    asm("{ .reg .u64 t; cvta.to.shared.u64 t, %1; cvt.u32.u64 %0, t; }"
        : "=r"(a) : "l"(p));
    return a;
}
__device__ __forceinline__ void cp16(uint32_t dst, const void* src) {
    asm volatile("cp.async.cg.shared.global [%0], [%1], 16;"
                 :: "r"(dst), "l"(src) : "memory");
}
__device__ __forceinline__ void cp_commit() {
    asm volatile("cp.async.commit_group;" ::: "memory");
}
__device__ __forceinline__ void cp_wait1() {
    asm volatile("cp.async.wait_group 1;" ::: "memory");
}
__device__ __forceinline__ void cp_wait0() {
    asm volatile("cp.async.wait_group 0;" ::: "memory");
}

#define LDM_X4(r0, r1, r2, r3, a)                                              \
    asm volatile("ldmatrix.sync.aligned.m8n8.x4.shared.b16 {%0,%1,%2,%3},[%4];"\
                 : "=r"(r0), "=r"(r1), "=r"(r2), "=r"(r3) : "r"(a))
#define LDM_X4T(r0, r1, r2, r3, a)                                             \
    asm volatile(                                                              \
        "ldmatrix.sync.aligned.m8n8.x4.trans.shared.b16 {%0,%1,%2,%3},[%4];"   \
        : "=r"(r0), "=r"(r1), "=r"(r2), "=r"(r3) : "r"(a))

#define MMA_FP16(c, a, b)                                                      \
    asm volatile(                                                              \
        "mma.sync.aligned.m16n8k16.row.col.f32.f16.f16.f32 "                   \
        "{%0,%1,%2,%3},{%4,%5,%6,%7},{%8,%9},{%0,%1,%2,%3};"                   \
        : "+f"((c)[0]), "+f"((c)[1]), "+f"((c)[2]), "+f"((c)[3])               \
        : "r"((a)[0]), "r"((a)[1]), "r"((a)[2]), "r"((a)[3]),                  \
          "r"((b)[0]), "r"((b)[1]))

__device__ __forceinline__ uint32_t pack16(uint16_t a, uint16_t b) {
    return ((uint32_t)b << 16) | (uint32_t)a;
}
__device__ __forceinline__ void split2h(float a, float b, uint32_t& hi, uint32_t& lo) {
    __half ha = __float2half_rn(a), hb = __float2half_rn(b);
    __half la = __float2half_rn(a - __half2float(ha));
    __half lb = __float2half_rn(b - __half2float(hb));
    hi = pack16(*(uint16_t*)&ha, *(uint16_t*)&hb);
    lo = pack16(*(uint16_t*)&la, *(uint16_t*)&lb);
}

// ---------------- conversions (one grid, y selects tensor) -----------------
__global__ __launch_bounds__(256) void cvt_all(const float4* __restrict__ x,
                                               const float4* __restrict__ Wq,
                                               const float4* __restrict__ Wk,
                                               const float4* __restrict__ Wv,
                                               const float4* __restrict__ Wp) {
    int i = blockIdx.x * blockDim.x + threadIdx.x;
    if (i >= TT * DIMM / 4) return;
    const int y = blockIdx.y;
    if (y == 0) {
        float4 v = x[i];
        __half fh[4], fl[4];
#pragma unroll
        for (int e = 0; e < 4; e++) {
            float f = (&v.x)[e];
            fh[e] = __float2half_rn(f);
            fl[e] = __float2half_rn(f - __half2float(fh[e]));
        }
        ((uint2*)g_xfh)[i] = *(uint2*)fh;
        ((uint2*)g_xfl)[i] = *(uint2*)fl;
    } else {
        const float4* src = (y == 1) ? Wq : (y == 2) ? Wk : (y == 3) ? Wv : Wp;
        __half* hi = (y == 1) ? g_wqfh : (y == 2) ? g_wkfh
                   : (y == 3) ? g_wvfh : g_wpfh;
        float4 v = src[i];
        __half fh[4];
#pragma unroll
        for (int e = 0; e < 4; e++) fh[e] = __float2half_rn((&v.x)[e]);
        ((uint2*)hi)[i] = *(uint2*)fh;
    }
}

// ---------------- fp16 2-term GEMM: C = (Ah+Al) @ Bh^T, K-chunk 64 ---------
#define GROW   144                 // 128B data + 16B pad per 128-row tile row
#define GTILE  (128 * GROW)        // 18432
#define GSTAGE (3 * GTILE)         // Ah, Al, Bh = 55296
#define GSMEM  (2 * GSTAGE)        // 110592 (occupancy 2: 221KB < 228KB)

__device__ __forceinline__ void g2_load_chunk(
    uint32_t base, const __half* Ah, const __half* Al, const __half* Bh,
    int mBase, int nBase, int kc, int tid) {
#pragma unroll
    for (int j = 0; j < 12; j++) {
        const int t = j >> 2;
        const int rem = tid + (j & 3) * 256;   // 0..1023
        const int r = rem >> 3;
        const int u = rem & 7;
        const __half* s = (t == 0) ? Ah : (t == 1) ? Al : Bh;
        const int rb = (t < 2) ? mBase : nBase;
        cp16(base + t * GTILE + r * GROW + u * 16,
             s + (size_t)(rb + r) * DIMM + kc + u * 8);
    }
}

__device__ __forceinline__ void gemm2_mma(const __half* Ah, const __half* Al,
                                          const __half* Bh, float* __restrict__ C) {
    extern __shared__ char sm[];
    const uint32_t smb = smem_u32(sm);
    const int tid = threadIdx.x;
    const int wid = tid >> 5;
    const int lane = tid & 31;
    const int mBase = blockIdx.y * 128;
    const int nBase = blockIdx.x * 128;
    const int wm = (wid >> 2) * 64;
    const int wn = (wid & 3) * 32;

    const int row16 = lane & 15;
    const int col16 = (lane >> 4) * 16;

    float acc[4][4][4];
#pragma unroll
    for (int i = 0; i < 4; i++)
#pragma unroll
        for (int n = 0; n < 4; n++)
#pragma unroll
            for (int v = 0; v < 4; v++) acc[i][n][v] = 0.0f;

    g2_load_chunk(smb, Ah, Al, Bh, mBase, nBase, 0, tid);
    cp_commit();

    for (int c = 0; c < 32; c++) {
        const uint32_t cur = smb + (c & 1) * GSTAGE;
        if (c + 1 < 32) {
            g2_load_chunk(smb + ((c + 1) & 1) * GSTAGE, Ah, Al, Bh,
                          mBase, nBase, (c + 1) * 64, tid);
            cp_commit();
            cp_wait1();
        } else {
            cp_wait0();
        }
        __syncthreads();

        const uint32_t Ab = cur;
        const uint32_t Alb = cur + GTILE;
        const uint32_t Bb = cur + 2 * GTILE;

#pragma unroll
        for (int s = 0; s < 4; s++) {
            uint32_t ah[4][4], al2[4][4], bh[4][2];
#pragma unroll
            for (int i = 0; i < 4; i++)
                LDM_X4(ah[i][0], ah[i][1], ah[i][2], ah[i][3],
                       Ab + (wm + i * 16 + row16) * GROW + s * 32 + col16);
#pragma unroll
            for (int n = 0; n < 2; n++) {
                uint32_t t0, t1, t2, t3;
                LDM_X4(t0, t1, t2, t3,
                       Bb + (wn + n * 16 + row16) * GROW + s * 32 + col16);
                bh[2 * n][0] = t0; bh[2 * n][1] = t2;
                bh[2 * n + 1][0] = t1; bh[2 * n + 1][1] = t3;
            }
#pragma unroll
            for (int i = 0; i < 4; i++)
#pragma unroll
                for (int n = 0; n < 4; n++) MMA_FP16(acc[i][n], ah[i], bh[n]);

#pragma unroll
            for (int i = 0; i < 4; i++)
                LDM_X4(al2[i][0], al2[i][1], al2[i][2], al2[i][3],
                       Alb + (wm + i * 16 + row16) * GROW + s * 32 + col16);
#pragma unroll
            for (int i = 0; i < 4; i++)
#pragma unroll
                for (int n = 0; n < 4; n++) MMA_FP16(acc[i][n], al2[i], bh[n]);
        }
        __syncthreads();
    }

    const int r0 = mBase + wm + (lane >> 2);
    const int c0 = nBase + wn + (lane & 3) * 2;
#pragma unroll
    for (int i = 0; i < 4; i++)
#pragma unroll
        for (int n = 0; n < 4; n++) {
            *(float2*)&C[(size_t)(r0 + i * 16) * DIMM + c0 + n * 8] =
                make_float2(acc[i][n][0], acc[i][n][1]);
            *(float2*)&C[(size_t)(r0 + i * 16 + 8) * DIMM + c0 + n * 8] =
                make_float2(acc[i][n][2], acc[i][n][3]);
        }
}

__global__ __launch_bounds__(256, 2) void qkv_mma() {
    if (blockIdx.z == 0)      gemm2_mma(g_xfh, g_xfl, g_wqfh, g_q);
    else if (blockIdx.z == 1) gemm2_mma(g_xfh, g_xfl, g_wkfh, g_k);
    else                      gemm2_mma(g_xfh, g_xfl, g_wvfh, g_v);
}

__global__ __launch_bounds__(256, 2) void proj_mma(float* __restrict__ out) {
    gemm2_mma(g_afh, g_afl, g_wpfh, out);
}

// ---------------- RoPE cos/sin table ---------------------------------------
__global__ void rope_table() {
    int idx = blockIdx.x * blockDim.x + threadIdx.x;
    if (idx >= TT * 64) return;
    int t = idx >> 6;
    int i = idx & 63;
    float e = (float)(2 * i) * (1.0f / 128.0f);
    float invf = 1.0f / powf(10000.0f, e);
    float fr = (float)t * invf;
    g_cos[idx] = (float)cos((double)fr);
    g_sin[idx] = (float)sin((double)fr);
}

// ------- v-mix (-> fp16) + per-head RMS norm + RoPE (-> fp16 hi/lo) --------
__global__ __launch_bounds__(256) void post_qkv(const float* __restrict__ v1,
                                                const float* __restrict__ lambp) {
    const int t = blockIdx.x;
    const int tid = threadIdx.x;
    const float lamb = *lambp;

    const float* vrow = g_v + (size_t)t * DIMM;
    const float* v1row = v1 + (size_t)t * DIMM;
    uint32_t* vhp = (uint32_t*)g_vfh + (size_t)t * DIMM / 2;
    for (int i = tid; i < DIMM / 2; i += 256) {
        float a = (1.0f - lamb) * vrow[2 * i] + lamb * v1row[2 * i];
        float b = (1.0f - lamb) * vrow[2 * i + 1] + lamb * v1row[2 * i + 1];
        __half ha = __float2half_rn(a), hb = __float2half_rn(b);
        vhp[i] = pack16(*(uint16_t*)&ha, *(uint16_t*)&hb);
    }

    const int warp = tid >> 5;
    const int lane = tid & 31;

    for (int hh = warp; hh < 2 * NH; hh += 8) {
        const int head = hh >> 1;
        const int isK = hh & 1;
        const float* p = (isK ? g_k : g_q) + (size_t)t * DIMM + head * HD;
        uint32_t* dsth = (uint32_t*)(isK ? g_kfh : g_qfh) +
                         ((size_t)t * DIMM + head * HD) / 2;
        uint32_t* dstl = (uint32_t*)g_qfl + ((size_t)t * DIMM + head * HD) / 2;

        float4 f = *(const float4*)&p[lane * 4];
        float ss = f.x * f.x + f.y * f.y + f.z * f.z + f.w * f.w;
#pragma unroll
        for (int off = 16; off; off >>= 1) ss += __shfl_xor_sync(0xffffffffu, ss, off);
        float sc = rsqrtf(ss * (1.0f / 128.0f) + EPSF);
        __syncwarp();

        const int i0 = 2 * lane;
        float x1a = p[i0] * sc,     x2a = p[i0 + 64] * sc;
        float x1b = p[i0 + 1] * sc, x2b = p[i0 + 65] * sc;
        float ca = g_cos[t * 64 + i0], sa = g_sin[t * 64 + i0];
        float cb = g_cos[t * 64 + i0 + 1], sb = g_sin[t * 64 + i0 + 1];
        float y1a = x1a * ca + x2a * sa, y2a = x2a * ca - x1a * sa;
        float y1b = x1b * cb + x2b * sb, y2b = x2b * cb - x1b * sb;
        uint32_t hi, lo;
        split2h(y1a, y1b, hi, lo);
        dsth[lane] = hi;
        if (!isK) dstl[lane] = lo;
        split2h(y2a, y2b, hi, lo);
        dsth[lane + 32] = hi;
        if (!isK) dstl[lane + 32] = lo;
    }
}

// ---------------- flash attention (fp16 2-term S, fp16 2-term PV) ----------
#define FROW   272
#define FTILE  (64 * FROW)
#define FSTAGE (2 * FTILE)         // Kh, Vh (fp16)
#define FSMEM  (2 * FSTAGE)

__device__ __forceinline__ void f_load_stage(uint32_t base, int s0, int h, int tid) {
#pragma unroll
    for (int t = 0; t < 2; t++) {
        const __half* src = (t == 0) ? g_kfh : g_vfh;
#pragma unroll
        for (int j = 0; j < 4; j++) {
            int idx = tid + j * 256;
            int r = idx >> 4, u = idx & 15;
            cp16(base + t * FTILE + r * FROW + u * 16,
                 src + (size_t)(s0 + r) * DIMM + h * HD + u * 8);
        }
    }
}

__global__ __launch_bounds__(256, 1) void flash_mma() {
    extern __shared__ char sm[];
    const uint32_t smb = smem_u32(sm);
    const int h = blockIdx.y;
    const int qb = gridDim.x - 1 - blockIdx.x;
    const int q0 = qb * 128;
    const int tid = threadIdx.x;
    const int wid = tid >> 5;
    const int lane = tid & 31;
    const int wm = wid * 16;

    uint32_t qh[8][4], ql[8][4];
    {
        const uint32_t* qhp = (const uint32_t*)g_qfh;
        const uint32_t* qlp = (const uint32_t*)g_qfl;
        const int r0 = q0 + wm + (lane >> 2);
        const int cb = h * HD + (lane & 3) * 2;
#pragma unroll
        for (int ks = 0; ks < 8; ks++) {
            uint32_t i00 = ((uint32_t)r0 * DIMM + cb + ks * 16) >> 1;
            uint32_t i10 = i00 + 8 * (DIMM / 2);
            qh[ks][0] = qhp[i00];     qh[ks][1] = qhp[i10];
            qh[ks][2] = qhp[i00 + 4]; qh[ks][3] = qhp[i10 + 4];
            ql[ks][0] = qlp[i00];     ql[ks][1] = qlp[i10];
            ql[ks][2] = qlp[i00 + 4]; ql[ks][3] = qlp[i10 + 4];
        }
    }

    float o[16][4];
#pragma unroll
    for (int n = 0; n < 16; n++)
#pragma unroll
        for (int v = 0; v < 4; v++) o[n][v] = 0.0f;
    float m[2] = {-INFINITY, -INFINITY};
    float l[2] = {0.0f, 0.0f};

    const int nkb = 2 * qb + 2;
    const float scale2 = 0.08838834764831845f * 1.4426950408889634f;

    f_load_stage(smb, 0, h, tid);
    cp_commit();

    const int row16 = lane & 15;
    const int col16 = (lane >> 4) * 16;

    for (int kb = 0; kb < nkb; kb++) {
        const uint32_t cur = smb + (kb & 1) * FSTAGE;
        if (kb + 1 < nkb) {
            f_load_stage(smb + ((kb + 1) & 1) * FSTAGE, (kb + 1) * 64, h, tid);
            cp_commit();
            cp_wait1();
        } else {
            cp_wait0();
        }
        __syncthreads();

        const int s0 = kb * 64;
        const uint32_t Kh = cur;
        const uint32_t Vh = cur + FTILE;

        float sc_[8][4];
#pragma unroll
        for (int n = 0; n < 8; n++)
#pragma unroll
            for (int v = 0; v < 4; v++) sc_[n][v] = 0.0f;

#pragma unroll
        for (int ks = 0; ks < 8; ks++) {
#pragma unroll
            for (int np = 0; np < 4; np++) {
                uint32_t bh[2][2];
                uint32_t t0, t1, t2, t3;
                LDM_X4(t0, t1, t2, t3,
                       Kh + (np * 16 + row16) * FROW + ks * 32 + col16);
                bh[0][0] = t0; bh[0][1] = t2; bh[1][0] = t1; bh[1][1] = t3;
                MMA_FP16(sc_[2 * np], qh[ks], bh[0]);
                MMA_FP16(sc_[2 * np], ql[ks], bh[0]);
                MMA_FP16(sc_[2 * np + 1], qh[ks], bh[1]);
                MMA_FP16(sc_[2 * np + 1], ql[ks], bh[1]);
            }
        }

        if (s0 + 63 > q0 + wm) {
            const int r0 = q0 + wm + (lane >> 2);
#pragma unroll
            for (int n = 0; n < 8; n++) {
                int c0 = s0 + n * 8 + (lane & 3) * 2;
#pragma unroll
                for (int e = 0; e < 2; e++) {
                    sc_[n][e]     = (c0 + e <= r0)     ? sc_[n][e] * scale2     : -1e30f;
                    sc_[n][e + 2] = (c0 + e <= r0 + 8) ? sc_[n][e + 2] * scale2 : -1e30f;
                }
            }
        } else {
#pragma unroll
            for (int n = 0; n < 8; n++)
#pragma unroll
                for (int v = 0; v < 4; v++) sc_[n][v] *= scale2;
        }

        float alpha[2];
#pragma unroll
        for (int e = 0; e < 2; e++) {
            float mt = m[e];
#pragma unroll
            for (int n = 0; n < 8; n++)
                mt = fmaxf(mt, fmaxf(sc_[n][2 * e], sc_[n][2 * e + 1]));
            mt = fmaxf(mt, __shfl_xor_sync(0xffffffffu, mt, 1));
            mt = fmaxf(mt, __shfl_xor_sync(0xffffffffu, mt, 2));
            alpha[e] = exp2f(m[e] - mt);
            m[e] = mt;
            float sum = 0.0f;
#pragma unroll
            for (int n = 0; n < 8; n++) {
                float p0 = exp2f(sc_[n][2 * e] - mt);
                float p1 = exp2f(sc_[n][2 * e + 1] - mt);
                sc_[n][2 * e] = p0;
                sc_[n][2 * e + 1] = p1;
                sum += p0 + p1;
            }
            sum += __shfl_xor_sync(0xffffffffu, sum, 1);
            sum += __shfl_xor_sync(0xffffffffu, sum, 2);
            l[e] = l[e] * alpha[e] + sum;
        }
#pragma unroll
        for (int n = 0; n < 16; n++) {
            o[n][0] *= alpha[0];
            o[n][1] *= alpha[0];
            o[n][2] *= alpha[1];
            o[n][3] *= alpha[1];
        }

        uint32_t ph[4][4], pl[4][4];
#pragma unroll
        for (int ks = 0; ks < 4; ks++) {
            split2h(sc_[2 * ks][0],     sc_[2 * ks][1],     ph[ks][0], pl[ks][0]);
            split2h(sc_[2 * ks][2],     sc_[2 * ks][3],     ph[ks][1], pl[ks][1]);
            split2h(sc_[2 * ks + 1][0], sc_[2 * ks + 1][1], ph[ks][2], pl[ks][2]);
            split2h(sc_[2 * ks + 1][2], sc_[2 * ks + 1][3], ph[ks][3], pl[ks][3]);
        }

#pragma unroll
        for (int ks = 0; ks < 4; ks++) {
#pragma unroll
            for (int np = 0; np < 8; np++) {
                uint32_t v2[2][2];
                uint32_t t0, t1, t2, t3;
                LDM_X4T(t0, t1, t2, t3,
                        Vh + (ks * 16 + row16) * FROW + np * 32 + col16);
                v2[0][0] = t0; v2[0][1] = t1; v2[1][0] = t2; v2[1][1] = t3;
                MMA_FP16(o[2 * np], ph[ks], v2[0]);
                MMA_FP16(o[2 * np], pl[ks], v2[0]);
                MMA_FP16(o[2 * np + 1], ph[ks], v2[1]);
                MMA_FP16(o[2 * np + 1], pl[ks], v2[1]);
            }
        }
        __syncthreads();
    }

    const float linv0 = 1.0f / l[0];
    const float linv1 = 1.0f / l[1];
    uint32_t* ahp = (uint32_t*)g_afh;
    uint32_t* alp = (uint32_t*)g_afl;
    const int r0 = q0 + wm + (lane >> 2);
    const int cb = h * HD + (lane & 3) * 2;
#pragma unroll
    for (int n = 0; n < 16; n++) {
        uint32_t i0 = ((uint32_t)r0 * DIMM + cb + n * 8) >> 1;
        uint32_t i1 = i0 + 8 * (DIMM / 2);
        uint32_t hi, lo;
        split2h(o[n][0] * linv0, o[n][1] * linv0, hi, lo);
        ahp[i0] = hi; alp[i0] = lo;
        split2h(o[n][2] * linv1, o[n][3] * linv1, hi, lo);
        ahp[i1] = hi; alp[i1] = lo;
    }
}

// ---------------- v1 passthrough -------------------------------------------
__global__ void copy_v1(const float4* __restrict__ src, float4* __restrict__ dst, int n4) {
    int idx = blockIdx.x * blockDim.x + threadIdx.x;
    if (idx < n4) dst[idx] = src[idx];
}

// ---------------- launch ----------------------------------------------------
extern "C" void kernel_launch(void* const* d_in, const int* in_sizes, int n_in,
                              void* d_out, int out_size) {
    const float* x = (const float*)d_in[0];
    const float* v1 = (const float*)d_in[1];
    const float* Wq = (const float*)d_in[2];
    const float* Wk = (const float*)d_in[3];
    const float* Wv = (const float*)d_in[4];
    const float* Wp = (const float*)d_in[5];
    const float* lamb = (const float*)d_in[6];
    float* out = (float*)d_out;

    cudaFuncSetAttribute(qkv_mma, cudaFuncAttributeMaxDynamicSharedMemorySize, GSMEM);
    cudaFuncSetAttribute(proj_mma, cudaFuncAttributeMaxDynamicSharedMemorySize, GSMEM);
    cudaFuncSetAttribute(flash_mma, cudaFuncAttributeMaxDynamicSharedMemorySize, FSMEM);

    rope_table<<<(TT * 64 + 255) / 256, 256>>>();

    const int n4 = TT * DIMM / 4;
    dim3 gcvt((n4 + 255) / 256, 5);
    cvt_all<<<gcvt, 256>>>((const float4*)x, (const float4*)Wq, (const float4*)Wk,
                           (const float4*)Wv, (const float4*)Wp);

    dim3 gqkv(DIMM / 128, TT / 128, 3);
    qkv_mma<<<gqkv, 256, GSMEM>>>();

    post_qkv<<<TT, 256>>>(v1, lamb);

    dim3 gfl(TT / 128, NH);
    flash_mma<<<gfl, 256, FSMEM>>>();

    dim3 gproj(DIMM / 128, TT / 128);
    proj_mma<<<gproj, 256, GSMEM>>>(out);

    if (out_size >= 2 * TT * DIMM) {
        copy_v1<<<(TT * DIMM / 4 + 255) / 256, 256>>>(
            (const float4*)v1, (float4*)(out + (size_t)TT * DIMM), TT * DIMM / 4);
    }
}